// round 6
// baseline (speedup 1.0000x reference)
#include <cuda_runtime.h>
#include <cuda_fp16.h>
#include <cstdint>
#include <cstddef>

// ---------------------------------------------------------------------------
// SmallSpatialPolicyHead — HMMA everywhere, ldmatrix frags, fused LN.
//   k_prep : repack weights (k2 node-proj hi/lo; k1 trunk-proj hi/lo)
//   k1     : HMMA trunk GEMM (M=128/CTA, N=208, K=80) + LN + BN partials
//   k_bn   : finalize BN scale/shift
//   k2     : per 2-batch-rows fused node kernel
//   k3     : BN + mish + gfc2, 4-row batched (ALIGNED smem this time)
// ---------------------------------------------------------------------------

#define BMAX 16384
#define K2_GRID 296
#define K3_GRID 592

__device__ float d_tb[208];
__device__ __half d_Wh[160 * 48];    // k2 node proj hi  [n][k]
__device__ __half d_Wl[160 * 48];    // k2 node proj lo
__device__ __half d_Wth[208 * 80];   // k1 trunk proj hi [o][k]
__device__ __half d_Wtl[208 * 80];   // k1 trunk proj lo
__device__ float d_tproj[(size_t)BMAX * 128];
__device__ float d_h[(size_t)BMAX * 80];
__device__ float d_partial[296 * 160];
__device__ float d_bnscale[80];
__device__ float d_bnshift[80];

// ---- k2 smem byte offsets ----
#define SM_XP    0             // xs 108x52 f (overlay) / P_s 108x98 f = 42336
#define SM_AH    42336         // 128x56 fp16 = 14336
#define SM_AL    56672
#define SM_WH    71008         // 160x56 fp16 = 17920
#define SM_WL    88928
#define WLOFF    17920
#define SM_TPROJ 106848        // 256 f
#define SM_W2    107872        // 96 f
#define SM_ROB2  108256        // 160 f
#define SM_B2    108896        // 8 f
#define SM_LNW   108928        // 48 f
#define SM_LNB   109120        // 48 f
#define SM_RP    109312        // 144 i
#define SM_TI    109888        // 114 i
#define SM_TOTAL 110344

// ---- k1 smem byte offsets ----
#define X1_XS    0             // 128x84 f = 43008 (reused as hs)
#define X1_AH    43008         // 128x88 fp16 = 22528
#define X1_AL    65536
#define X1_WH    88064         // 208x88 fp16 = 36608
#define X1_WL    124672
#define W1OFF    36608
#define X1_TB    161280        // 208 f
#define X1_LNW   162112        // 80 f
#define X1_LNB   162432        // 80 f
#define K1_SMEM  162752

__device__ __forceinline__ uint32_t smem_u32(const void* p) {
    uint32_t a;
    asm("{ .reg .u64 t; cvta.to.shared.u64 t, %1; cvt.u32.u64 %0, t; }" : "=r"(a) : "l"(p));
    return a;
}
__device__ __forceinline__ void cp16(uint32_t dst, const void* src) {
    asm volatile("cp.async.cg.shared.global [%0], [%1], 16;" :: "r"(dst), "l"(src));
}
#define CP_COMMIT_WAIT() do { \
    asm volatile("cp.async.commit_group;" ::: "memory"); \
    asm volatile("cp.async.wait_group 0;" ::: "memory"); } while (0)

#define LDSM_X4(r0,r1,r2,r3,addr) \
    asm volatile("ldmatrix.sync.aligned.m8n8.x4.shared.b16 {%0,%1,%2,%3}, [%4];" \
        : "=r"(r0),"=r"(r1),"=r"(r2),"=r"(r3) : "r"(addr))
#define LDSM_X2(r0,r1,addr) \
    asm volatile("ldmatrix.sync.aligned.m8n8.x2.shared.b16 {%0,%1}, [%2];" \
        : "=r"(r0),"=r"(r1) : "r"(addr))

__device__ __forceinline__ void mma16816(float* d, const uint32_t* a, uint32_t b0, uint32_t b1) {
    asm volatile(
        "mma.sync.aligned.m16n8k16.row.col.f32.f16.f16.f32 "
        "{%0,%1,%2,%3},{%4,%5,%6,%7},{%8,%9},{%0,%1,%2,%3};"
        : "+f"(d[0]), "+f"(d[1]), "+f"(d[2]), "+f"(d[3])
        : "r"(a[0]), "r"(a[1]), "r"(a[2]), "r"(a[3]), "r"(b0), "r"(b1));
}

__device__ __forceinline__ float mishf(float x) {
    float u = __expf(fminf(x, 15.f));
    float d = __fmaf_rn(u, u + 2.f, 2.f);
    return x - __fdividef(2.f * x, d);
}
__device__ __forceinline__ float warp_sum(float v) {
    #pragma unroll
    for (int o = 16; o; o >>= 1) v += __shfl_xor_sync(0xffffffffu, v, o);
    return v;
}

// ------------------------------ prep ------------------------------
__global__ void k_prep(const float* __restrict__ sett1_w, const float* __restrict__ city1_w,
                       const float* __restrict__ road1_w, const float* __restrict__ rob1_w,
                       const float* __restrict__ gfc1_w,
                       const float* __restrict__ sett1_b, const float* __restrict__ city1_b,
                       const float* __restrict__ road1_b, const float* __restrict__ rob1_b,
                       const float* __restrict__ gfc1_b) {
    int i = blockIdx.x * blockDim.x + threadIdx.x;
    if (i < 160 * 48) {          // k2 node-proj W[n][k], hi/lo
        int j = i / 48, k = i % 48;
        float v;
        if (j < 32)       v = sett1_w[j * 128 + 80 + k];
        else if (j < 64)  v = city1_w[(j - 32) * 128 + 80 + k];
        else if (j < 96)  v = road1_w[(j - 64) * 176 + 80 + k];
        else if (j < 128) v = road1_w[(j - 96) * 176 + 128 + k];
        else              v = rob1_w[(j - 128) * 128 + 80 + k];
        __half h = __float2half(v);
        d_Wh[i] = h;
        d_Wl[i] = __float2half(v - __half2float(h));
    }
    if (i < 208 * 80) {          // k1 trunk-proj W[o][k], hi/lo
        int o = i / 80, k = i % 80;
        float v;
        if (o < 32)       v = sett1_w[o * 128 + k];
        else if (o < 64)  v = city1_w[(o - 32) * 128 + k];
        else if (o < 96)  v = road1_w[(o - 64) * 176 + k];
        else if (o < 128) v = rob1_w[(o - 96) * 128 + k];
        else              v = gfc1_w[(o - 128) * 80 + k];
        __half h = __float2half(v);
        d_Wth[i] = h;
        d_Wtl[i] = __float2half(v - __half2float(h));
    }
    if (i < 208) {
        float v;
        if (i < 32)       v = sett1_b[i];
        else if (i < 64)  v = city1_b[i - 32];
        else if (i < 96)  v = road1_b[i - 64];
        else if (i < 128) v = rob1_b[i - 96];
        else              v = gfc1_b[i - 128];
        d_tb[i] = v;
    }
}

// ------------------------------ K1: HMMA trunk kernel ------------------------------
__global__ __launch_bounds__(512, 1) void k1(const float* __restrict__ trunk,
                                             const float* __restrict__ ln_t_w,
                                             const float* __restrict__ ln_t_b, int B) {
    extern __shared__ char smem[];
    const uint32_t sbase = smem_u32(smem);
    const int tid = threadIdx.x, wid = tid >> 5, lane = tid & 31;

    float* xs  = (float*)(smem + X1_XS);      // staging, reused as hs
    float* hs  = (float*)(smem + X1_XS);
    float* tb_s = (float*)(smem + X1_TB);
    float* lnw = (float*)(smem + X1_LNW);
    float* lnb = (float*)(smem + X1_LNB);

    for (int i = tid; i < 208 * 80; i += 512) {
        int o = i / 80, k = i % 80;
        *(__half*)(smem + X1_WH + (o * 88 + k) * 2) = d_Wth[i];
        *(__half*)(smem + X1_WL + (o * 88 + k) * 2) = d_Wtl[i];
    }
    for (int i = tid; i < 208; i += 512) tb_s[i] = d_tb[i];
    if (tid < 80) { lnw[tid] = ln_t_w[tid]; lnb[tid] = ln_t_b[tid]; }

    const int rows_valid = min(128, B - (int)blockIdx.x * 128);

    // stage trunk rows (128 x 80 f) into xs stride 84
    {
        const float4* tr4 = (const float4*)trunk;
        size_t base4 = (size_t)blockIdx.x * 2560;
        #pragma unroll
        for (int q = 0; q < 5; q++) {
            int il = tid + q * 512;
            int row = il / 20, c = il % 20;
            if (row < rows_valid)
                cp16(sbase + X1_XS + (uint32_t)((row * 84 + 4 * c) * 4), tr4 + base4 + il);
        }
        CP_COMMIT_WAIT();
    }
    __syncthreads();

    // fused LN: thread-pair per row, write AH/AL (stride 88 halfs)
    if (tid < 256) {
        const int r = tid >> 1, h = tid & 1;
        float4 v[10];
        if (r < rows_valid) {
            const float4* xr = (const float4*)(xs + r * 84 + h * 40);
            #pragma unroll
            for (int j = 0; j < 10; j++) v[j] = xr[j];
        } else {
            #pragma unroll
            for (int j = 0; j < 10; j++) v[j] = make_float4(0.f, 0.f, 0.f, 0.f);
        }
        float s = 0.f, q = 0.f;
        #pragma unroll
        for (int j = 0; j < 10; j++) {
            s += v[j].x + v[j].y + v[j].z + v[j].w;
            q += v[j].x * v[j].x + v[j].y * v[j].y + v[j].z * v[j].z + v[j].w * v[j].w;
        }
        s += __shfl_xor_sync(0xffffffffu, s, 1);
        q += __shfl_xor_sync(0xffffffffu, q, 1);
        float mu = s * (1.f / 80.f);
        float is = rsqrtf(q * (1.f / 80.f) - mu * mu + 1e-5f);
        char* dh = smem + X1_AH + (r * 88 + h * 40) * 2;
        char* dl = dh + (X1_AL - X1_AH);
        const float4* lw4 = (const float4*)(lnw + h * 40);
        const float4* lb4 = (const float4*)(lnb + h * 40);
        #pragma unroll
        for (int j = 0; j < 10; j++) {
            float4 w = lw4[j], b = lb4[j];
            float a0 = (v[j].x - mu) * is * w.x + b.x;
            float a1 = (v[j].y - mu) * is * w.y + b.y;
            float a2 = (v[j].z - mu) * is * w.z + b.z;
            float a3 = (v[j].w - mu) * is * w.w + b.w;
            if (r >= rows_valid) { a0 = a1 = a2 = a3 = 0.f; }
            __half2 h01 = __floats2half2_rn(a0, a1), h23 = __floats2half2_rn(a2, a3);
            __half2 l01 = __floats2half2_rn(a0 - __low2float(h01), a1 - __high2float(h01));
            __half2 l23 = __floats2half2_rn(a2 - __low2float(h23), a3 - __high2float(h23));
            uint2 uh; uh.x = *(uint32_t*)&h01; uh.y = *(uint32_t*)&h23;
            uint2 ul; ul.x = *(uint32_t*)&l01; ul.y = *(uint32_t*)&l23;
            *(uint2*)(dh + j * 8) = uh;
            *(uint2*)(dl + j * 8) = ul;
        }
    }
    __syncthreads();

    // MMA: warp -> m-tile (wid&7), n-half (wid>>3): 13 nt x 5 ks x 3 terms
    {
        const int mt = wid & 7, nh = wid >> 3;
        const int g = lane >> 2, k0 = (lane & 3) * 2;
        const uint32_t abase = sbase + X1_AH +
            (uint32_t)((mt * 16 + (lane & 15)) * 176 + (lane >> 4) * 16);
        uint32_t ah[5][4];
        #pragma unroll
        for (int ks = 0; ks < 5; ks++)
            LDSM_X4(ah[ks][0], ah[ks][1], ah[ks][2], ah[ks][3], abase + ks * 32);

        uint32_t wx4 = sbase + X1_WH +
            (uint32_t)((lane & 7) * 176 + (lane >> 3) * 16) + (uint32_t)(nh * 13 * 1408);
        uint32_t wx2 = sbase + X1_WH +
            (uint32_t)((lane & 7) * 176 + ((lane >> 3) & 1) * 16 + 128) + (uint32_t)(nh * 13 * 1408);

        #pragma unroll
        for (int ni = 0; ni < 13; ni++) {
            const int nt = nh * 13 + ni;
            uint32_t bhA[4], bhB[4], bh2[2], blA[4], blB[4], bl2[2];
            LDSM_X4(bhA[0], bhA[1], bhA[2], bhA[3], wx4);
            LDSM_X4(bhB[0], bhB[1], bhB[2], bhB[3], wx4 + 64);
            LDSM_X2(bh2[0], bh2[1], wx2);
            LDSM_X4(blA[0], blA[1], blA[2], blA[3], wx4 + W1OFF);
            LDSM_X4(blB[0], blB[1], blB[2], blB[3], wx4 + 64 + W1OFF);
            LDSM_X2(bl2[0], bl2[1], wx2 + W1OFF);

            float acc[4] = {0.f, 0.f, 0.f, 0.f};
            mma16816(acc, ah[0], bhA[0], bhA[1]);
            mma16816(acc, ah[1], bhA[2], bhA[3]);
            mma16816(acc, ah[2], bhB[0], bhB[1]);
            mma16816(acc, ah[3], bhB[2], bhB[3]);
            mma16816(acc, ah[4], bh2[0], bh2[1]);
            mma16816(acc, ah[0], blA[0], blA[1]);
            mma16816(acc, ah[1], blA[2], blA[3]);
            mma16816(acc, ah[2], blB[0], blB[1]);
            mma16816(acc, ah[3], blB[2], blB[3]);
            mma16816(acc, ah[4], bl2[0], bl2[1]);
            {
                uint32_t al[4];
                const uint32_t albase = abase + (X1_AL - X1_AH);
                LDSM_X4(al[0], al[1], al[2], al[3], albase);
                mma16816(acc, al, bhA[0], bhA[1]);
                LDSM_X4(al[0], al[1], al[2], al[3], albase + 32);
                mma16816(acc, al, bhA[2], bhA[3]);
                LDSM_X4(al[0], al[1], al[2], al[3], albase + 64);
                mma16816(acc, al, bhB[0], bhB[1]);
                LDSM_X4(al[0], al[1], al[2], al[3], albase + 96);
                mma16816(acc, al, bhB[2], bhB[3]);
                LDSM_X4(al[0], al[1], al[2], al[3], albase + 128);
                mma16816(acc, al, bh2[0], bh2[1]);
            }
            wx4 += 1408; wx2 += 1408;

            const int col = nt * 8 + k0;
            const int row0 = mt * 16 + g, row1 = row0 + 8;
            if (col < 128) {
                float b0 = tb_s[col], b1 = tb_s[col + 1];
                if (row0 < rows_valid) {
                    size_t o = (size_t)((size_t)blockIdx.x * 128 + row0) * 128 + col;
                    d_tproj[o] = acc[0] + b0; d_tproj[o + 1] = acc[1] + b1;
                }
                if (row1 < rows_valid) {
                    size_t o = (size_t)((size_t)blockIdx.x * 128 + row1) * 128 + col;
                    d_tproj[o] = acc[2] + b0; d_tproj[o + 1] = acc[3] + b1;
                }
            } else {
                const int ch = col - 128;
                hs[row0 * 84 + ch] = acc[0]; hs[row0 * 84 + ch + 1] = acc[1];
                hs[row1 * 84 + ch] = acc[2]; hs[row1 * 84 + ch + 1] = acc[3];
                if (row0 < rows_valid) {
                    size_t o = (size_t)((size_t)blockIdx.x * 128 + row0) * 80 + ch;
                    d_h[o] = acc[0]; d_h[o + 1] = acc[1];
                }
                if (row1 < rows_valid) {
                    size_t o = (size_t)((size_t)blockIdx.x * 128 + row1) * 80 + ch;
                    d_h[o] = acc[2]; d_h[o + 1] = acc[3];
                }
            }
        }
    }
    __syncthreads();

    // BN partials (deterministic per-CTA; bias folds out of BN algebraically)
    if (tid < 80) {
        float s1 = 0.f, s2 = 0.f;
        for (int r = 0; r < rows_valid; r++) {
            float v = hs[r * 84 + tid];
            s1 += v; s2 += v * v;
        }
        d_partial[blockIdx.x * 160 + tid] = s1;
        d_partial[blockIdx.x * 160 + 80 + tid] = s2;
    }
}

// ------------------------------ BN finalize ------------------------------
__global__ void k_bn(const float* __restrict__ bn_w, const float* __restrict__ bn_b,
                     int B, int nblk) {
    int t = threadIdx.x;
    if (t >= 80) return;
    float S1 = 0.f, S2 = 0.f;
    for (int blk = 0; blk < nblk; blk++) {
        S1 += d_partial[blk * 160 + t];
        S2 += d_partial[blk * 160 + 80 + t];
    }
    float invB = 1.f / (float)B;
    float mu = S1 * invB;
    float var = S2 * invB - mu * mu;
    float sc = bn_w[t] * rsqrtf(var + 1e-5f);
    d_bnscale[t] = sc;
    d_bnshift[t] = bn_b[t] - mu * sc;
}

// ------------------------------ K2: HMMA fused node kernel ------------------------------
__global__ __launch_bounds__(256, 2) void k2(const float* __restrict__ node_emb,
                                             const float* __restrict__ ln_n_w,
                                             const float* __restrict__ ln_n_b,
                                             const int* __restrict__ road_pairs,
                                             const int* __restrict__ tile_nodes,
                                             const float* __restrict__ sett2_w, const float* __restrict__ sett2_b,
                                             const float* __restrict__ city2_w, const float* __restrict__ city2_b,
                                             const float* __restrict__ road2_w, const float* __restrict__ road2_b,
                                             const float* __restrict__ rob2_w, const float* __restrict__ rob2_b,
                                             float* __restrict__ out, int B) {
    extern __shared__ char smem[];
    const uint32_t sbase = smem_u32(smem);
    const int tid = threadIdx.x, wid = tid >> 5, lane = tid & 31;

    float* xs      = (float*)(smem + SM_XP);   // rows x 52 (overlay)
    float* P_s     = (float*)(smem + SM_XP);   // rows x 98
    float* tproj_s = (float*)(smem + SM_TPROJ);
    float* w2_s    = (float*)(smem + SM_W2);
    float* rob2_s  = (float*)(smem + SM_ROB2);
    float* b2_s    = (float*)(smem + SM_B2);
    float* lnw     = (float*)(smem + SM_LNW);
    float* lnb     = (float*)(smem + SM_LNB);
    int*   rp_s    = (int*)(smem + SM_RP);
    int*   ti_s    = (int*)(smem + SM_TI);

    for (int i = tid; i < 160 * 48; i += 256) {
        int n = i / 48, k = i % 48;
        *(__half*)(smem + SM_WH + (n * 56 + k) * 2) = d_Wh[i];
        *(__half*)(smem + SM_WL + (n * 56 + k) * 2) = d_Wl[i];
    }
    if (tid < 48) { lnw[tid] = ln_n_w[tid]; lnb[tid] = ln_n_b[tid]; }
    if (tid < 32) { w2_s[tid] = sett2_w[tid]; w2_s[32 + tid] = city2_w[tid]; w2_s[64 + tid] = road2_w[tid]; }
    if (tid < 160) rob2_s[tid] = rob2_w[tid];
    if (tid == 0) { b2_s[0] = sett2_b[0]; b2_s[1] = city2_b[0]; b2_s[2] = road2_b[0]; }
    if (tid < 5) b2_s[3 + tid] = rob2_b[tid];
    if (tid < 144) rp_s[tid] = road_pairs[tid];
    if (tid < 114) ti_s[tid] = tile_nodes[tid];

    const int g = lane >> 2;
    const int k0 = (lane & 3) * 2;
    const int mrow = (wid & 3) * 32;
    const int nbase = (wid >> 2) * 10;

    int rown[4]; const float* tpp[4];
    #pragma unroll
    for (int s = 0; s < 4; s++) {
        rown[s] = mrow + 16 * (s >> 1) + 8 * (s & 1) + g;
        tpp[s] = tproj_s + ((rown[s] >= 54) ? 128 : 0);
    }

    uint32_t sdst[6];
    #pragma unroll
    for (int q = 0; q < 6; q++) {
        int il = tid + q * 256;
        int row = il / 12, c = il % 12;
        sdst[q] = sbase + SM_XP + (uint32_t)((row * 52 + 4 * c) * 4);
    }
    const uint32_t sdstT = sbase + SM_TPROJ + (uint32_t)(tid * 16);

    const uint32_t abase = sbase + SM_AH +
        (uint32_t)((mrow + (lane & 15)) * 112 + (lane >> 4) * 16);
    const uint32_t wx4base = sbase + SM_WH +
        (uint32_t)((lane & 7) * 112 + (lane >> 3) * 16) + (uint32_t)(nbase * 896);
    const uint32_t wx2base = sbase + SM_WH +
        (uint32_t)((lane & 7) * 112 + ((lane >> 3) & 1) * 16 + 64) + (uint32_t)(nbase * 896);

    const long npairs = ((long)B + 1) / 2;
    const size_t tot4 = (size_t)B * 648;
    const size_t totp4 = (size_t)B * 32;
    const float4* ne4 = (const float4*)node_emb;
    const float4* tp4 = (const float4*)d_tproj;

    for (long pair = blockIdx.x; pair < npairs; pair += gridDim.x) {
        // ---- stage ----
        if (2 * pair + 2 <= (long)B) {
            const float4* src = ne4 + (size_t)pair * 1296;
            #pragma unroll
            for (int q = 0; q < 5; q++) cp16(sdst[q], src + tid + q * 256);
            if (tid < 16) cp16(sdst[5], src + tid + 1280);
            if (tid < 64) cp16(sdstT, tp4 + (size_t)pair * 64 + tid);
        } else {
            size_t base4 = (size_t)pair * 1296;
            #pragma unroll
            for (int q = 0; q < 6; q++) {
                int il = tid + q * 256;
                if (il < 1296 && base4 + il < tot4) cp16(sdst[q], ne4 + base4 + il);
            }
            if (tid < 64 && (size_t)pair * 64 + tid < totp4)
                cp16(sdstT, tp4 + (size_t)pair * 64 + tid);
        }
        CP_COMMIT_WAIT();
        __syncthreads();

        const int nrows = (int)((long)B * 54 - pair * 108 >= 108 ? 108 : (long)B * 54 - pair * 108);

        // ---- fused LN: thread-pair per row ----
        {
            const int r = tid >> 1, h = tid & 1;
            const float4* xr = (const float4*)(xs + r * 52 + h * 24);
            float4 v[6];
            #pragma unroll
            for (int j = 0; j < 6; j++) v[j] = xr[j];
            float s = 0.f, q = 0.f;
            #pragma unroll
            for (int j = 0; j < 6; j++) {
                s += v[j].x + v[j].y + v[j].z + v[j].w;
                q += v[j].x * v[j].x + v[j].y * v[j].y + v[j].z * v[j].z + v[j].w * v[j].w;
            }
            s += __shfl_xor_sync(0xffffffffu, s, 1);
            q += __shfl_xor_sync(0xffffffffu, q, 1);
            float mu = s * (1.f / 48.f);
            float is = rsqrtf(q * (1.f / 48.f) - mu * mu + 1e-5f);
            if (r < 108) {
                char* dh = smem + SM_AH + (r * 56 + h * 24) * 2;
                char* dl = dh + (SM_AL - SM_AH);
                const float4* lw4 = (const float4*)(lnw + h * 24);
                const float4* lb4 = (const float4*)(lnb + h * 24);
                #pragma unroll
                for (int j = 0; j < 6; j++) {
                    float4 w = lw4[j], b = lb4[j];
                    float a0 = (v[j].x - mu) * is * w.x + b.x;
                    float a1 = (v[j].y - mu) * is * w.y + b.y;
                    float a2 = (v[j].z - mu) * is * w.z + b.z;
                    float a3 = (v[j].w - mu) * is * w.w + b.w;
                    __half2 h01 = __floats2half2_rn(a0, a1), h23 = __floats2half2_rn(a2, a3);
                    __half2 l01 = __floats2half2_rn(a0 - __low2float(h01), a1 - __high2float(h01));
                    __half2 l23 = __floats2half2_rn(a2 - __low2float(h23), a3 - __high2float(h23));
                    uint2 uh; uh.x = *(uint32_t*)&h01; uh.y = *(uint32_t*)&h23;
                    uint2 ul; ul.x = *(uint32_t*)&l01; ul.y = *(uint32_t*)&l23;
                    *(uint2*)(dh + j * 8) = uh;
                    *(uint2*)(dl + j * 8) = ul;
                }
            }
        }
        __syncthreads();

        // ---- A frags via ldmatrix ----
        uint32_t afh[2][3][4], afl[2][3][4];
        #pragma unroll
        for (int t = 0; t < 2; t++)
            #pragma unroll
            for (int ks = 0; ks < 3; ks++) {
                uint32_t ad = abase + t * 1792 + ks * 32;
                LDSM_X4(afh[t][ks][0], afh[t][ks][1], afh[t][ks][2], afh[t][ks][3], ad);
                LDSM_X4(afl[t][ks][0], afl[t][ks][1], afl[t][ks][2], afl[t][ks][3],
                        ad + (SM_AL - SM_AH));
            }

        float sacc[4] = {0.f, 0.f, 0.f, 0.f}, cacc[4] = {0.f, 0.f, 0.f, 0.f};
        uint32_t wx4 = wx4base, wx2 = wx2base;

        #pragma unroll
        for (int ni = 0; ni < 10; ni++) {
            const int nt = nbase + ni;
            uint32_t bh[4], bh2[2], bl[4], bl2[2];
            LDSM_X4(bh[0], bh[1], bh[2], bh[3], wx4);
            LDSM_X2(bh2[0], bh2[1], wx2);
            LDSM_X4(bl[0], bl[1], bl[2], bl[3], wx4 + WLOFF);
            LDSM_X2(bl2[0], bl2[1], wx2 + WLOFF);
            wx4 += 896; wx2 += 896;

            float acc[2][4] = {{0.f, 0.f, 0.f, 0.f}, {0.f, 0.f, 0.f, 0.f}};
            #pragma unroll
            for (int t = 0; t < 2; t++) {
                mma16816(acc[t], afh[t][0], bh[0], bh[1]);
                mma16816(acc[t], afh[t][1], bh[2], bh[3]);
                mma16816(acc[t], afh[t][2], bh2[0], bh2[1]);
                mma16816(acc[t], afh[t][0], bl[0], bl[1]);
                mma16816(acc[t], afh[t][1], bl[2], bl[3]);
                mma16816(acc[t], afh[t][2], bl2[0], bl2[1]);
                mma16816(acc[t], afl[t][0], bh[0], bh[1]);
                mma16816(acc[t], afl[t][1], bh[2], bh[3]);
                mma16816(acc[t], afl[t][2], bh2[0], bh2[1]);
            }

            const int col = nt * 8 + k0;
            if (nt < 8) {
                float w2a = w2_s[col], w2b = w2_s[col + 1];
                float* dst = (nt < 4) ? sacc : cacc;
                #pragma unroll
                for (int s = 0; s < 4; s++) {
                    float v0 = acc[s >> 1][2 * (s & 1)];
                    float v1 = acc[s >> 1][2 * (s & 1) + 1];
                    dst[s] += mishf(v0 + tpp[s][col]) * w2a + mishf(v1 + tpp[s][col + 1]) * w2b;
                }
            } else {
                #pragma unroll
                for (int s = 0; s < 4; s++) {
                    int r = rown[s];
                    if (r < 108)
                        *(float2*)(P_s + r * 98 + (col - 64)) =
                            make_float2(acc[s >> 1][2 * (s & 1)], acc[s >> 1][2 * (s & 1) + 1]);
                }
            }
        }

        // sett/city finalize (warps 0-3 cover cols 0:64)
        if (wid < 4) {
            #pragma unroll
            for (int s = 0; s < 4; s++) {
                sacc[s] += __shfl_xor_sync(0xffffffffu, sacc[s], 1);
                sacc[s] += __shfl_xor_sync(0xffffffffu, sacc[s], 2);
                cacc[s] += __shfl_xor_sync(0xffffffffu, cacc[s], 1);
                cacc[s] += __shfl_xor_sync(0xffffffffu, cacc[s], 2);
            }
            if ((lane & 3) == 0) {
                #pragma unroll
                for (int s = 0; s < 4; s++) {
                    int r = rown[s];
                    if (r < nrows) {
                        int bl = (r >= 54) ? 1 : 0;
                        int n = r - 54 * bl;
                        size_t ob = ((size_t)(pair * 2 + bl)) * 397;
                        out[ob + 5 + n]  = sacc[s] + b2_s[0];
                        out[ob + 59 + n] = cacc[s] + b2_s[1];
                    }
                }
            }
        }
        __syncthreads();

        // ---- heads ----
        const int nb = (nrows > 54) ? 2 : 1;
        #pragma unroll 2
        for (int t = wid; t < nb * 72; t += 8) {
            int bl = (t >= 72) ? 1 : 0;
            int e = t - 72 * bl;
            int sN = rp_s[2 * e], dN = rp_s[2 * e + 1];
            float hv = tproj_s[bl * 128 + 64 + lane]
                     + P_s[(bl * 54 + sN) * 98 + lane]
                     + P_s[(bl * 54 + dN) * 98 + 32 + lane];
            float red = warp_sum(mishf(hv) * w2_s[64 + lane]);
            if (lane == 0) out[((size_t)(pair * 2 + bl)) * 397 + 113 + e] = red + b2_s[2];
        }
        for (int t = wid; t < nb * 19; t += 8) {
            int bl = (t >= 19) ? 1 : 0;
            int tt = t - 19 * bl;
            float a = 0.f;
            #pragma unroll
            for (int i = 0; i < 6; i++)
                a += P_s[(bl * 54 + ti_s[tt * 6 + i]) * 98 + 64 + lane];
            float m = mishf(tproj_s[bl * 128 + 96 + lane] + a * (1.f / 6.f));
            #pragma unroll
            for (int o = 0; o < 5; o++) {
                float red = warp_sum(m * rob2_s[o * 32 + lane]);
                if (lane == 0)
                    out[((size_t)(pair * 2 + bl)) * 397 + 185 + tt * 5 + o] = red + b2_s[3 + o];
            }
        }
        __syncthreads();   // protect xs/P_s overlay before next staging
    }
}

// ------------------------------ K3: BN + mish + gfc2, 4-row batched ------------------------------
__global__ __launch_bounds__(128) void k3(const float* __restrict__ gfc2_w,
                                          const float* __restrict__ gfc2_b,
                                          float* __restrict__ out, int B) {
    __shared__ __align__(16) float m4[80 * 4];   // FIRST + aligned: float4-read safe
    __shared__ __align__(16) float Wg[80 * 122];
    __shared__ float bs[122];
    __shared__ float sc[80], sh[80];
    int tid = threadIdx.x;
    for (int i = tid; i < 80 * 122; i += 128) {
        int k = i / 122, t = i % 122;
        int r = (t < 5) ? t : (275 + t);
        Wg[i] = gfc2_w[r * 80 + k];
    }
    if (tid < 122) { int r = (tid < 5) ? tid : (275 + tid); bs[tid] = gfc2_b[r]; }
    if (tid < 80) { sc[tid] = d_bnscale[tid]; sh[tid] = d_bnshift[tid]; }
    __syncthreads();
    int nq = (B + 3) >> 2;
    for (int qb = blockIdx.x; qb < nq; qb += gridDim.x) {
        if (tid < 80) {
            #pragma unroll
            for (int rb = 0; rb < 4; rb++) {
                int b = qb * 4 + rb;
                float v = (b < B) ? d_h[(size_t)b * 80 + tid] : 0.f;
                m4[tid * 4 + rb] = mishf(v * sc[tid] + sh[tid]);
            }
        }
        __syncthreads();
        if (tid < 122) {
            float a0 = bs[tid], a1 = a0, a2 = a0, a3 = a0;
            for (int k = 0; k < 80; k++) {
                float4 m = *(const float4*)(m4 + k * 4);
                float w = Wg[k * 122 + tid];
                a0 += m.x * w; a1 += m.y * w; a2 += m.z * w; a3 += m.w * w;
            }
            int col = (tid < 5) ? tid : (275 + tid);
            int b = qb * 4;
            if (b < B)     out[(size_t)b * 397 + col] = a0;
            if (b + 1 < B) out[(size_t)(b + 1) * 397 + col] = a1;
            if (b + 2 < B) out[(size_t)(b + 2) * 397 + col] = a2;
            if (b + 3 < B) out[(size_t)(b + 3) * 397 + col] = a3;
        }
        __syncthreads();
    }
}

// ------------------------------ launch ------------------------------
extern "C" void kernel_launch(void* const* d_in, const int* in_sizes, int n_in,
                              void* d_out, int out_size) {
    const float* trunk      = (const float*)d_in[0];
    const float* node_emb   = (const float*)d_in[1];
    const int*   road_pairs = (const int*)d_in[2];
    const int*   tile_nodes = (const int*)d_in[3];
    const float* ln_t_w = (const float*)d_in[4];
    const float* ln_t_b = (const float*)d_in[5];
    const float* ln_n_w = (const float*)d_in[6];
    const float* ln_n_b = (const float*)d_in[7];
    const float* gfc1_w = (const float*)d_in[8];
    const float* gfc1_b = (const float*)d_in[9];
    const float* bn_w   = (const float*)d_in[10];
    const float* bn_b   = (const float*)d_in[11];
    const float* gfc2_w = (const float*)d_in[12];
    const float* gfc2_b = (const float*)d_in[13];
    const float* sett1_w = (const float*)d_in[14];
    const float* sett1_b = (const float*)d_in[15];
    const float* sett2_w = (const float*)d_in[16];
    const float* sett2_b = (const float*)d_in[17];
    const float* city1_w = (const float*)d_in[18];
    const float* city1_b = (const float*)d_in[19];
    const float* city2_w = (const float*)d_in[20];
    const float* city2_b = (const float*)d_in[21];
    const float* road1_w = (const float*)d_in[22];
    const float* road1_b = (const float*)d_in[23];
    const float* road2_w = (const float*)d_in[24];
    const float* road2_b = (const float*)d_in[25];
    const float* rob1_w = (const float*)d_in[26];
    const float* rob1_b = (const float*)d_in[27];
    const float* rob2_w = (const float*)d_in[28];
    const float* rob2_b = (const float*)d_in[29];

    int B = in_sizes[0] / 80;
    if (B > BMAX) B = BMAX;
    float* out = (float*)d_out;
    int nblk1 = (B + 127) / 128;

    cudaFuncSetAttribute(k1, cudaFuncAttributeMaxDynamicSharedMemorySize, K1_SMEM);
    cudaFuncSetAttribute(k2, cudaFuncAttributeMaxDynamicSharedMemorySize, SM_TOTAL);

    k_prep<<<(208 * 80 + 255) / 256, 256>>>(sett1_w, city1_w, road1_w, rob1_w, gfc1_w,
                                            sett1_b, city1_b, road1_b, rob1_b, gfc1_b);
    k1<<<nblk1, 512, K1_SMEM>>>(trunk, ln_t_w, ln_t_b, B);
    k_bn<<<1, 80>>>(bn_w, bn_b, B, nblk1);
    k2<<<K2_GRID, 256, SM_TOTAL>>>(node_emb, ln_n_w, ln_n_b, road_pairs, tile_nodes,
                                   sett2_w, sett2_b, city2_w, city2_b,
                                   road2_w, road2_b, rob2_w, rob2_b, out, B);
    k3<<<K3_GRID, 128>>>(gfc2_w, gfc2_b, out, B);
}

// round 7
// speedup vs baseline: 1.4336x; 1.4336x over previous
#include <cuda_runtime.h>
#include <cuda_fp16.h>
#include <cstdint>
#include <cstddef>

// ---------------------------------------------------------------------------
// SmallSpatialPolicyHead — R4 k2 (proven) + R6 HMMA k1 / batched k3.
// ---------------------------------------------------------------------------

#define BMAX 16384
#define K2_GRID 296
#define K3_GRID 592

__device__ float d_tb[208];
__device__ __half d_Wh[160 * 48];    // k2 node proj hi  [n][k]
__device__ __half d_Wl[160 * 48];    // k2 node proj lo
__device__ __half d_Wth[208 * 80];   // k1 trunk proj hi [o][k]
__device__ __half d_Wtl[208 * 80];   // k1 trunk proj lo
__device__ float d_tproj[(size_t)BMAX * 128];
__device__ float d_h[(size_t)BMAX * 80];
__device__ float d_partial[296 * 160];
__device__ float d_bnscale[80];
__device__ float d_bnshift[80];

// ---- k2 smem byte offsets (R4 layout) ----
#define SM_XP    0             // xs 108x52 f (overlay) / P_s 108x97 f
#define SM_AH    42336         // 128x56 fp16 = 14336
#define SM_AL    56672
#define SM_WH    71008         // 160x56 fp16 = 17920
#define SM_WL    88928
#define SM_TPROJ 106848        // 256 f
#define SM_W2    107872        // 96 f
#define SM_ROB2  108256        // 160 f
#define SM_B2    108896        // 8 f
#define SM_LNW   108928        // 48 f
#define SM_LNB   109120        // 48 f
#define SM_MU    109312        // 108 f
#define SM_IS    109744        // 108 f
#define SM_RP    110176        // 144 i
#define SM_TI    110752        // 114 i
#define SM_TOTAL 111208

// ---- k1 smem byte offsets ----
#define X1_XS    0             // 128x84 f = 43008 (reused as hs)
#define X1_AH    43008         // 128x88 fp16 = 22528
#define X1_AL    65536
#define X1_WH    88064         // 208x88 fp16 = 36608
#define X1_WL    124672
#define W1OFF    36608
#define X1_TB    161280        // 208 f
#define X1_LNW   162112        // 80 f
#define X1_LNB   162432        // 80 f
#define K1_SMEM  162752

__device__ __forceinline__ uint32_t smem_u32(const void* p) {
    uint32_t a;
    asm("{ .reg .u64 t; cvta.to.shared.u64 t, %1; cvt.u32.u64 %0, t; }" : "=r"(a) : "l"(p));
    return a;
}
__device__ __forceinline__ void cp16(uint32_t dst, const void* src) {
    asm volatile("cp.async.cg.shared.global [%0], [%1], 16;" :: "r"(dst), "l"(src));
}
#define CP_COMMIT_WAIT() do { \
    asm volatile("cp.async.commit_group;" ::: "memory"); \
    asm volatile("cp.async.wait_group 0;" ::: "memory"); } while (0)

#define LDSM_X4(r0,r1,r2,r3,addr) \
    asm volatile("ldmatrix.sync.aligned.m8n8.x4.shared.b16 {%0,%1,%2,%3}, [%4];" \
        : "=r"(r0),"=r"(r1),"=r"(r2),"=r"(r3) : "r"(addr))
#define LDSM_X2(r0,r1,addr) \
    asm volatile("ldmatrix.sync.aligned.m8n8.x2.shared.b16 {%0,%1}, [%2];" \
        : "=r"(r0),"=r"(r1) : "r"(addr))

__device__ __forceinline__ void mma16816(float* d, const uint32_t* a, uint32_t b0, uint32_t b1) {
    asm volatile(
        "mma.sync.aligned.m16n8k16.row.col.f32.f16.f16.f32 "
        "{%0,%1,%2,%3},{%4,%5,%6,%7},{%8,%9},{%0,%1,%2,%3};"
        : "+f"(d[0]), "+f"(d[1]), "+f"(d[2]), "+f"(d[3])
        : "r"(a[0]), "r"(a[1]), "r"(a[2]), "r"(a[3]), "r"(b0), "r"(b1));
}

__device__ __forceinline__ float mishf(float x) {
    float u = __expf(fminf(x, 15.f));
    float d = __fmaf_rn(u, u + 2.f, 2.f);
    return x - __fdividef(2.f * x, d);
}
__device__ __forceinline__ float warp_sum(float v) {
    #pragma unroll
    for (int o = 16; o; o >>= 1) v += __shfl_xor_sync(0xffffffffu, v, o);
    return v;
}

// ------------------------------ prep ------------------------------
__global__ void k_prep(const float* __restrict__ sett1_w, const float* __restrict__ city1_w,
                       const float* __restrict__ road1_w, const float* __restrict__ rob1_w,
                       const float* __restrict__ gfc1_w,
                       const float* __restrict__ sett1_b, const float* __restrict__ city1_b,
                       const float* __restrict__ road1_b, const float* __restrict__ rob1_b,
                       const float* __restrict__ gfc1_b) {
    int i = blockIdx.x * blockDim.x + threadIdx.x;
    if (i < 160 * 48) {          // k2 node-proj W[n][k], hi/lo
        int j = i / 48, k = i % 48;
        float v;
        if (j < 32)       v = sett1_w[j * 128 + 80 + k];
        else if (j < 64)  v = city1_w[(j - 32) * 128 + 80 + k];
        else if (j < 96)  v = road1_w[(j - 64) * 176 + 80 + k];
        else if (j < 128) v = road1_w[(j - 96) * 176 + 128 + k];
        else              v = rob1_w[(j - 128) * 128 + 80 + k];
        __half h = __float2half(v);
        d_Wh[i] = h;
        d_Wl[i] = __float2half(v - __half2float(h));
    }
    if (i < 208 * 80) {          // k1 trunk-proj W[o][k], hi/lo
        int o = i / 80, k = i % 80;
        float v;
        if (o < 32)       v = sett1_w[o * 128 + k];
        else if (o < 64)  v = city1_w[(o - 32) * 128 + k];
        else if (o < 96)  v = road1_w[(o - 64) * 176 + k];
        else if (o < 128) v = rob1_w[(o - 96) * 128 + k];
        else              v = gfc1_w[(o - 128) * 80 + k];
        __half h = __float2half(v);
        d_Wth[i] = h;
        d_Wtl[i] = __float2half(v - __half2float(h));
    }
    if (i < 208) {
        float v;
        if (i < 32)       v = sett1_b[i];
        else if (i < 64)  v = city1_b[i - 32];
        else if (i < 96)  v = road1_b[i - 64];
        else if (i < 128) v = rob1_b[i - 96];
        else              v = gfc1_b[i - 128];
        d_tb[i] = v;
    }
}

// ------------------------------ K1: HMMA trunk kernel (R6, proven) ------------------------------
__global__ __launch_bounds__(512, 1) void k1(const float* __restrict__ trunk,
                                             const float* __restrict__ ln_t_w,
                                             const float* __restrict__ ln_t_b, int B) {
    extern __shared__ char smem[];
    const uint32_t sbase = smem_u32(smem);
    const int tid = threadIdx.x, wid = tid >> 5, lane = tid & 31;

    float* xs  = (float*)(smem + X1_XS);
    float* hs  = (float*)(smem + X1_XS);
    float* tb_s = (float*)(smem + X1_TB);
    float* lnw = (float*)(smem + X1_LNW);
    float* lnb = (float*)(smem + X1_LNB);

    for (int i = tid; i < 208 * 80; i += 512) {
        int o = i / 80, k = i % 80;
        *(__half*)(smem + X1_WH + (o * 88 + k) * 2) = d_Wth[i];
        *(__half*)(smem + X1_WL + (o * 88 + k) * 2) = d_Wtl[i];
    }
    for (int i = tid; i < 208; i += 512) tb_s[i] = d_tb[i];
    if (tid < 80) { lnw[tid] = ln_t_w[tid]; lnb[tid] = ln_t_b[tid]; }

    const int rows_valid = min(128, B - (int)blockIdx.x * 128);

    {
        const float4* tr4 = (const float4*)trunk;
        size_t base4 = (size_t)blockIdx.x * 2560;
        #pragma unroll
        for (int q = 0; q < 5; q++) {
            int il = tid + q * 512;
            int row = il / 20, c = il % 20;
            if (row < rows_valid)
                cp16(sbase + X1_XS + (uint32_t)((row * 84 + 4 * c) * 4), tr4 + base4 + il);
        }
        CP_COMMIT_WAIT();
    }
    __syncthreads();

    if (tid < 256) {
        const int r = tid >> 1, h = tid & 1;
        float4 v[10];
        if (r < rows_valid) {
            const float4* xr = (const float4*)(xs + r * 84 + h * 40);
            #pragma unroll
            for (int j = 0; j < 10; j++) v[j] = xr[j];
        } else {
            #pragma unroll
            for (int j = 0; j < 10; j++) v[j] = make_float4(0.f, 0.f, 0.f, 0.f);
        }
        float s = 0.f, q = 0.f;
        #pragma unroll
        for (int j = 0; j < 10; j++) {
            s += v[j].x + v[j].y + v[j].z + v[j].w;
            q += v[j].x * v[j].x + v[j].y * v[j].y + v[j].z * v[j].z + v[j].w * v[j].w;
        }
        s += __shfl_xor_sync(0xffffffffu, s, 1);
        q += __shfl_xor_sync(0xffffffffu, q, 1);
        float mu = s * (1.f / 80.f);
        float is = rsqrtf(q * (1.f / 80.f) - mu * mu + 1e-5f);
        char* dh = smem + X1_AH + (r * 88 + h * 40) * 2;
        char* dl = dh + (X1_AL - X1_AH);
        const float4* lw4 = (const float4*)(lnw + h * 40);
        const float4* lb4 = (const float4*)(lnb + h * 40);
        #pragma unroll
        for (int j = 0; j < 10; j++) {
            float4 w = lw4[j], b = lb4[j];
            float a0 = (v[j].x - mu) * is * w.x + b.x;
            float a1 = (v[j].y - mu) * is * w.y + b.y;
            float a2 = (v[j].z - mu) * is * w.z + b.z;
            float a3 = (v[j].w - mu) * is * w.w + b.w;
            if (r >= rows_valid) { a0 = a1 = a2 = a3 = 0.f; }
            __half2 h01 = __floats2half2_rn(a0, a1), h23 = __floats2half2_rn(a2, a3);
            __half2 l01 = __floats2half2_rn(a0 - __low2float(h01), a1 - __high2float(h01));
            __half2 l23 = __floats2half2_rn(a2 - __low2float(h23), a3 - __high2float(h23));
            uint2 uh; uh.x = *(uint32_t*)&h01; uh.y = *(uint32_t*)&h23;
            uint2 ul; ul.x = *(uint32_t*)&l01; ul.y = *(uint32_t*)&l23;
            *(uint2*)(dh + j * 8) = uh;
            *(uint2*)(dl + j * 8) = ul;
        }
    }
    __syncthreads();

    {
        const int mt = wid & 7, nh = wid >> 3;
        const int g = lane >> 2, k0 = (lane & 3) * 2;
        const uint32_t abase = sbase + X1_AH +
            (uint32_t)((mt * 16 + (lane & 15)) * 176 + (lane >> 4) * 16);
        uint32_t ah[5][4];
        #pragma unroll
        for (int ks = 0; ks < 5; ks++)
            LDSM_X4(ah[ks][0], ah[ks][1], ah[ks][2], ah[ks][3], abase + ks * 32);

        uint32_t wx4 = sbase + X1_WH +
            (uint32_t)((lane & 7) * 176 + (lane >> 3) * 16) + (uint32_t)(nh * 13 * 1408);
        uint32_t wx2 = sbase + X1_WH +
            (uint32_t)((lane & 7) * 176 + ((lane >> 3) & 1) * 16 + 128) + (uint32_t)(nh * 13 * 1408);

        #pragma unroll
        for (int ni = 0; ni < 13; ni++) {
            const int nt = nh * 13 + ni;
            uint32_t bhA[4], bhB[4], bh2[2], blA[4], blB[4], bl2[2];
            LDSM_X4(bhA[0], bhA[1], bhA[2], bhA[3], wx4);
            LDSM_X4(bhB[0], bhB[1], bhB[2], bhB[3], wx4 + 64);
            LDSM_X2(bh2[0], bh2[1], wx2);
            LDSM_X4(blA[0], blA[1], blA[2], blA[3], wx4 + W1OFF);
            LDSM_X4(blB[0], blB[1], blB[2], blB[3], wx4 + 64 + W1OFF);
            LDSM_X2(bl2[0], bl2[1], wx2 + W1OFF);

            float acc[4] = {0.f, 0.f, 0.f, 0.f};
            mma16816(acc, ah[0], bhA[0], bhA[1]);
            mma16816(acc, ah[1], bhA[2], bhA[3]);
            mma16816(acc, ah[2], bhB[0], bhB[1]);
            mma16816(acc, ah[3], bhB[2], bhB[3]);
            mma16816(acc, ah[4], bh2[0], bh2[1]);
            mma16816(acc, ah[0], blA[0], blA[1]);
            mma16816(acc, ah[1], blA[2], blA[3]);
            mma16816(acc, ah[2], blB[0], blB[1]);
            mma16816(acc, ah[3], blB[2], blB[3]);
            mma16816(acc, ah[4], bl2[0], bl2[1]);
            {
                uint32_t al[4];
                const uint32_t albase = abase + (X1_AL - X1_AH);
                LDSM_X4(al[0], al[1], al[2], al[3], albase);
                mma16816(acc, al, bhA[0], bhA[1]);
                LDSM_X4(al[0], al[1], al[2], al[3], albase + 32);
                mma16816(acc, al, bhA[2], bhA[3]);
                LDSM_X4(al[0], al[1], al[2], al[3], albase + 64);
                mma16816(acc, al, bhB[0], bhB[1]);
                LDSM_X4(al[0], al[1], al[2], al[3], albase + 96);
                mma16816(acc, al, bhB[2], bhB[3]);
                LDSM_X4(al[0], al[1], al[2], al[3], albase + 128);
                mma16816(acc, al, bh2[0], bh2[1]);
            }
            wx4 += 1408; wx2 += 1408;

            const int col = nt * 8 + k0;
            const int row0 = mt * 16 + g, row1 = row0 + 8;
            if (col < 128) {
                float b0 = tb_s[col], b1 = tb_s[col + 1];
                if (row0 < rows_valid) {
                    size_t o = (size_t)((size_t)blockIdx.x * 128 + row0) * 128 + col;
                    d_tproj[o] = acc[0] + b0; d_tproj[o + 1] = acc[1] + b1;
                }
                if (row1 < rows_valid) {
                    size_t o = (size_t)((size_t)blockIdx.x * 128 + row1) * 128 + col;
                    d_tproj[o] = acc[2] + b0; d_tproj[o + 1] = acc[3] + b1;
                }
            } else {
                const int ch = col - 128;
                hs[row0 * 84 + ch] = acc[0]; hs[row0 * 84 + ch + 1] = acc[1];
                hs[row1 * 84 + ch] = acc[2]; hs[row1 * 84 + ch + 1] = acc[3];
                if (row0 < rows_valid) {
                    size_t o = (size_t)((size_t)blockIdx.x * 128 + row0) * 80 + ch;
                    d_h[o] = acc[0]; d_h[o + 1] = acc[1];
                }
                if (row1 < rows_valid) {
                    size_t o = (size_t)((size_t)blockIdx.x * 128 + row1) * 80 + ch;
                    d_h[o] = acc[2]; d_h[o + 1] = acc[3];
                }
            }
        }
    }
    __syncthreads();

    if (tid < 80) {
        float s1 = 0.f, s2 = 0.f;
        for (int r = 0; r < rows_valid; r++) {
            float v = hs[r * 84 + tid];
            s1 += v; s2 += v * v;
        }
        d_partial[blockIdx.x * 160 + tid] = s1;
        d_partial[blockIdx.x * 160 + 80 + tid] = s2;
    }
}

// ------------------------------ BN finalize ------------------------------
__global__ void k_bn(const float* __restrict__ bn_w, const float* __restrict__ bn_b,
                     int B, int nblk) {
    int t = threadIdx.x;
    if (t >= 80) return;
    float S1 = 0.f, S2 = 0.f;
    for (int blk = 0; blk < nblk; blk++) {
        S1 += d_partial[blk * 160 + t];
        S2 += d_partial[blk * 160 + 80 + t];
    }
    float invB = 1.f / (float)B;
    float mu = S1 * invB;
    float var = S2 * invB - mu * mu;
    float sc = bn_w[t] * rsqrtf(var + 1e-5f);
    d_bnscale[t] = sc;
    d_bnshift[t] = bn_b[t] - mu * sc;
}

// ------------------------------ K2: R4 HMMA fused node kernel (proven 424us) ------------------------------
__global__ __launch_bounds__(256, 2) void k2(const float* __restrict__ node_emb,
                                             const float* __restrict__ ln_n_w,
                                             const float* __restrict__ ln_n_b,
                                             const int* __restrict__ road_pairs,
                                             const int* __restrict__ tile_nodes,
                                             const float* __restrict__ sett2_w, const float* __restrict__ sett2_b,
                                             const float* __restrict__ city2_w, const float* __restrict__ city2_b,
                                             const float* __restrict__ road2_w, const float* __restrict__ road2_b,
                                             const float* __restrict__ rob2_w, const float* __restrict__ rob2_b,
                                             float* __restrict__ out, int B) {
    extern __shared__ char smem[];
    const uint32_t sbase = smem_u32(smem);
    const int tid = threadIdx.x, wid = tid >> 5, lane = tid & 31;

    float* xs      = (float*)(smem + SM_XP);   // rows x 52 (overlay)
    float* P_s     = (float*)(smem + SM_XP);   // rows x 97
    float* tproj_s = (float*)(smem + SM_TPROJ);
    float* w2_s    = (float*)(smem + SM_W2);
    float* rob2_s  = (float*)(smem + SM_ROB2);
    float* b2_s    = (float*)(smem + SM_B2);
    float* lnw     = (float*)(smem + SM_LNW);
    float* lnb     = (float*)(smem + SM_LNB);
    float* mu_s    = (float*)(smem + SM_MU);
    float* is_s    = (float*)(smem + SM_IS);
    int*   rp_s    = (int*)(smem + SM_RP);
    int*   ti_s    = (int*)(smem + SM_TI);

    for (int i = tid; i < 160 * 48; i += 256) {
        int n = i / 48, k = i % 48;
        *(__half*)(smem + SM_WH + (n * 56 + k) * 2) = d_Wh[i];
        *(__half*)(smem + SM_WL + (n * 56 + k) * 2) = d_Wl[i];
    }
    if (tid < 48) { lnw[tid] = ln_n_w[tid]; lnb[tid] = ln_n_b[tid]; }
    if (tid < 32) { w2_s[tid] = sett2_w[tid]; w2_s[32 + tid] = city2_w[tid]; w2_s[64 + tid] = road2_w[tid]; }
    if (tid < 160) rob2_s[tid] = rob2_w[tid];
    if (tid == 0) { b2_s[0] = sett2_b[0]; b2_s[1] = city2_b[0]; b2_s[2] = road2_b[0]; }
    if (tid < 5) b2_s[3 + tid] = rob2_b[tid];
    if (tid < 144) rp_s[tid] = road_pairs[tid];
    if (tid < 114) ti_s[tid] = tile_nodes[tid];

    const int g = lane >> 2;
    const int k0 = (lane & 3) * 2;
    const int mrow = (wid & 3) * 32;
    const int nbase = (wid >> 2) * 10;

    int rown[4]; const float* tpp[4];
    #pragma unroll
    for (int s = 0; s < 4; s++) {
        rown[s] = mrow + 16 * (s >> 1) + 8 * (s & 1) + g;
        tpp[s] = tproj_s + ((rown[s] >= 54) ? 128 : 0);
    }

    const long npairs = ((long)B + 1) / 2;
    const size_t tot4 = (size_t)B * 648;
    const size_t totp4 = (size_t)B * 32;
    const float4* ne4 = (const float4*)node_emb;
    const float4* tp4 = (const float4*)d_tproj;

    for (long pair = blockIdx.x; pair < npairs; pair += gridDim.x) {
        // ---- stage via cp.async: node rows into xs (stride 52), tproj ----
        {
            size_t base4 = (size_t)pair * 1296;
            #pragma unroll
            for (int q = 0; q < 6; q++) {
                int il = tid + q * 256;
                if (il < 1296 && base4 + il < tot4) {
                    int row = il / 12, c = il % 12;
                    cp16(sbase + SM_XP + (uint32_t)((row * 52 + 4 * c) * 4), ne4 + base4 + il);
                }
            }
            if (tid < 64) {
                size_t t4 = (size_t)pair * 64 + tid;
                if (t4 < totp4) cp16(sbase + SM_TPROJ + tid * 16, tp4 + t4);
            }
            CP_COMMIT_WAIT();
        }
        __syncthreads();

        const int nrows = (int)((long)B * 54 - pair * 108 >= 108 ? 108 : (long)B * 54 - pair * 108);

        // ---- LN phase A: thread-per-row sums ----
        if (tid < nrows) {
            const float4* xr = (const float4*)(xs + tid * 52);
            float s = 0.f, q = 0.f;
            #pragma unroll
            for (int j = 0; j < 12; j++) {
                float4 v = xr[j];
                s += v.x + v.y + v.z + v.w;
                q += v.x * v.x + v.y * v.y + v.z * v.z + v.w * v.w;
            }
            float mu = s * (1.f / 48.f);
            mu_s[tid] = mu;
            is_s[tid] = rsqrtf(q * (1.f / 48.f) - mu * mu + 1e-5f);
        }
        __syncthreads();

        // ---- LN phase B: vectorized split into AH/AL ----
        for (int i = tid; i < 2592; i += 256) {
            int r = i / 24, c2 = (i % 24) * 2;
            if (r < nrows) {
                float2 v = *(const float2*)(xs + r * 52 + c2);
                float mu = mu_s[r], is = is_s[r];
                float v0 = (v.x - mu) * is * lnw[c2] + lnb[c2];
                float v1 = (v.y - mu) * is * lnw[c2 + 1] + lnb[c2 + 1];
                __half2 h = __floats2half2_rn(v0, v1);
                __half2 l = __floats2half2_rn(v0 - __low2float(h), v1 - __high2float(h));
                *(__half2*)(smem + SM_AH + (r * 56 + c2) * 2) = h;
                *(__half2*)(smem + SM_AL + (r * 56 + c2) * 2) = l;
            }
        }
        __syncthreads();

        // ---- A fragments (plain LDS; compiler-scheduled) ----
        uint32_t afh[2][3][4], afl[2][3][4];
        #pragma unroll
        for (int t = 0; t < 2; t++) {
            #pragma unroll
            for (int ks = 0; ks < 3; ks++) {
                const char* ba = smem + SM_AH + ((mrow + 16 * t + g) * 56 + k0 + 16 * ks) * 2;
                afh[t][ks][0] = *(const uint32_t*)(ba);
                afh[t][ks][1] = *(const uint32_t*)(ba + 896);
                afh[t][ks][2] = *(const uint32_t*)(ba + 16);
                afh[t][ks][3] = *(const uint32_t*)(ba + 896 + 16);
                const char* bl = ba + (SM_AL - SM_AH);
                afl[t][ks][0] = *(const uint32_t*)(bl);
                afl[t][ks][1] = *(const uint32_t*)(bl + 896);
                afl[t][ks][2] = *(const uint32_t*)(bl + 16);
                afl[t][ks][3] = *(const uint32_t*)(bl + 896 + 16);
            }
        }

        float sacc[4] = {0.f, 0.f, 0.f, 0.f}, cacc[4] = {0.f, 0.f, 0.f, 0.f};

        #pragma unroll
        for (int ni = 0; ni < 10; ni++) {
            const int nt = nbase + ni;
            float acc[2][4] = {{0.f, 0.f, 0.f, 0.f}, {0.f, 0.f, 0.f, 0.f}};
            const char* wb = smem + SM_WH + ((nt * 8 + g) * 56 + k0) * 2;
            #pragma unroll
            for (int ks = 0; ks < 3; ks++) {
                uint32_t bh0 = *(const uint32_t*)(wb + 32 * ks);
                uint32_t bh1 = *(const uint32_t*)(wb + 32 * ks + 16);
                uint32_t bl0 = *(const uint32_t*)(wb + 32 * ks + (SM_WL - SM_WH));
                uint32_t bl1 = *(const uint32_t*)(wb + 32 * ks + 16 + (SM_WL - SM_WH));
                #pragma unroll
                for (int t = 0; t < 2; t++) {
                    mma16816(acc[t], afh[t][ks], bh0, bh1);
                    mma16816(acc[t], afh[t][ks], bl0, bl1);
                    mma16816(acc[t], afl[t][ks], bh0, bh1);
                }
            }
            const int col = nt * 8 + k0;
            if (nt < 8) {
                float w2a = w2_s[col], w2b = w2_s[col + 1];
                float* dst = (nt < 4) ? sacc : cacc;
                #pragma unroll
                for (int s = 0; s < 4; s++) {
                    float v0 = acc[s >> 1][2 * (s & 1)];
                    float v1 = acc[s >> 1][2 * (s & 1) + 1];
                    dst[s] += mishf(v0 + tpp[s][col]) * w2a + mishf(v1 + tpp[s][col + 1]) * w2b;
                }
            } else {
                #pragma unroll
                for (int s = 0; s < 4; s++) {
                    int r = rown[s];
                    if (r < 108) {
                        float* pr = P_s + r * 97 + (col - 64);
                        pr[0] = acc[s >> 1][2 * (s & 1)];
                        pr[1] = acc[s >> 1][2 * (s & 1) + 1];
                    }
                }
            }
        }

        // sett/city finalize (warps 0-3 cover cols 0:64)
        if (wid < 4) {
            #pragma unroll
            for (int s = 0; s < 4; s++) {
                sacc[s] += __shfl_xor_sync(0xffffffffu, sacc[s], 1);
                sacc[s] += __shfl_xor_sync(0xffffffffu, sacc[s], 2);
                cacc[s] += __shfl_xor_sync(0xffffffffu, cacc[s], 1);
                cacc[s] += __shfl_xor_sync(0xffffffffu, cacc[s], 2);
            }
            if ((lane & 3) == 0) {
                #pragma unroll
                for (int s = 0; s < 4; s++) {
                    int r = rown[s];
                    if (r < nrows) {
                        int bl = (r >= 54) ? 1 : 0;
                        int n = r - 54 * bl;
                        size_t ob = ((size_t)(pair * 2 + bl)) * 397;
                        out[ob + 5 + n]  = sacc[s] + b2_s[0];
                        out[ob + 59 + n] = cacc[s] + b2_s[1];
                    }
                }
            }
        }
        __syncthreads();

        const int nb = (nrows > 54) ? 2 : 1;
        for (int t = wid; t < nb * 72; t += 8) {
            int bl = t / 72, e = t - 72 * bl;
            int sN = rp_s[2 * e], dN = rp_s[2 * e + 1];
            float hv = tproj_s[bl * 128 + 64 + lane]
                     + P_s[(bl * 54 + sN) * 97 + lane]
                     + P_s[(bl * 54 + dN) * 97 + 32 + lane];
            float red = warp_sum(mishf(hv) * w2_s[64 + lane]);
            if (lane == 0) out[((size_t)(pair * 2 + bl)) * 397 + 113 + e] = red + b2_s[2];
        }
        for (int t = wid; t < nb * 19; t += 8) {
            int bl = t / 19, tt = t - 19 * bl;
            float a = 0.f;
            #pragma unroll
            for (int i = 0; i < 6; i++)
                a += P_s[(bl * 54 + ti_s[tt * 6 + i]) * 97 + 64 + lane];
            float m = mishf(tproj_s[bl * 128 + 96 + lane] + a * (1.f / 6.f));
            #pragma unroll
            for (int o = 0; o < 5; o++) {
                float red = warp_sum(m * rob2_s[o * 32 + lane]);
                if (lane == 0)
                    out[((size_t)(pair * 2 + bl)) * 397 + 185 + tt * 5 + o] = red + b2_s[3 + o];
            }
        }
        __syncthreads();   // protect xs/P_s overlay before next staging
    }
}

// ------------------------------ K3: BN + mish + gfc2, 4-row batched ------------------------------
__global__ __launch_bounds__(128) void k3(const float* __restrict__ gfc2_w,
                                          const float* __restrict__ gfc2_b,
                                          float* __restrict__ out, int B) {
    __shared__ __align__(16) float m4[80 * 4];
    __shared__ __align__(16) float Wg[80 * 122];
    __shared__ float bs[122];
    __shared__ float sc[80], sh[80];
    int tid = threadIdx.x;
    for (int i = tid; i < 80 * 122; i += 128) {
        int k = i / 122, t = i % 122;
        int r = (t < 5) ? t : (275 + t);
        Wg[i] = gfc2_w[r * 80 + k];
    }
    if (tid < 122) { int r = (tid < 5) ? tid : (275 + tid); bs[tid] = gfc2_b[r]; }
    if (tid < 80) { sc[tid] = d_bnscale[tid]; sh[tid] = d_bnshift[tid]; }
    __syncthreads();
    int nq = (B + 3) >> 2;
    for (int qb = blockIdx.x; qb < nq; qb += gridDim.x) {
        if (tid < 80) {
            #pragma unroll
            for (int rb = 0; rb < 4; rb++) {
                int b = qb * 4 + rb;
                float v = (b < B) ? d_h[(size_t)b * 80 + tid] : 0.f;
                m4[tid * 4 + rb] = mishf(v * sc[tid] + sh[tid]);
            }
        }
        __syncthreads();
        if (tid < 122) {
            float a0 = bs[tid], a1 = a0, a2 = a0, a3 = a0;
            for (int k = 0; k < 80; k++) {
                float4 m = *(const float4*)(m4 + k * 4);
                float w = Wg[k * 122 + tid];
                a0 += m.x * w; a1 += m.y * w; a2 += m.z * w; a3 += m.w * w;
            }
            int col = (tid < 5) ? tid : (275 + tid);
            int b = qb * 4;
            if (b < B)     out[(size_t)b * 397 + col] = a0;
            if (b + 1 < B) out[(size_t)(b + 1) * 397 + col] = a1;
            if (b + 2 < B) out[(size_t)(b + 2) * 397 + col] = a2;
            if (b + 3 < B) out[(size_t)(b + 3) * 397 + col] = a3;
        }
        __syncthreads();
    }
}

// ------------------------------ launch ------------------------------
extern "C" void kernel_launch(void* const* d_in, const int* in_sizes, int n_in,
                              void* d_out, int out_size) {
    const float* trunk      = (const float*)d_in[0];
    const float* node_emb   = (const float*)d_in[1];
    const int*   road_pairs = (const int*)d_in[2];
    const int*   tile_nodes = (const int*)d_in[3];
    const float* ln_t_w = (const float*)d_in[4];
    const float* ln_t_b = (const float*)d_in[5];
    const float* ln_n_w = (const float*)d_in[6];
    const float* ln_n_b = (const float*)d_in[7];
    const float* gfc1_w = (const float*)d_in[8];
    const float* gfc1_b = (const float*)d_in[9];
    const float* bn_w   = (const float*)d_in[10];
    const float* bn_b   = (const float*)d_in[11];
    const float* gfc2_w = (const float*)d_in[12];
    const float* gfc2_b = (const float*)d_in[13];
    const float* sett1_w = (const float*)d_in[14];
    const float* sett1_b = (const float*)d_in[15];
    const float* sett2_w = (const float*)d_in[16];
    const float* sett2_b = (const float*)d_in[17];
    const float* city1_w = (const float*)d_in[18];
    const float* city1_b = (const float*)d_in[19];
    const float* city2_w = (const float*)d_in[20];
    const float* city2_b = (const float*)d_in[21];
    const float* road1_w = (const float*)d_in[22];
    const float* road1_b = (const float*)d_in[23];
    const float* road2_w = (const float*)d_in[24];
    const float* road2_b = (const float*)d_in[25];
    const float* rob1_w = (const float*)d_in[26];
    const float* rob1_b = (const float*)d_in[27];
    const float* rob2_w = (const float*)d_in[28];
    const float* rob2_b = (const float*)d_in[29];

    int B = in_sizes[0] / 80;
    if (B > BMAX) B = BMAX;
    float* out = (float*)d_out;
    int nblk1 = (B + 127) / 128;

    cudaFuncSetAttribute(k1, cudaFuncAttributeMaxDynamicSharedMemorySize, K1_SMEM);
    cudaFuncSetAttribute(k2, cudaFuncAttributeMaxDynamicSharedMemorySize, SM_TOTAL);

    k_prep<<<(208 * 80 + 255) / 256, 256>>>(sett1_w, city1_w, road1_w, rob1_w, gfc1_w,
                                            sett1_b, city1_b, road1_b, rob1_b, gfc1_b);
    k1<<<nblk1, 512, K1_SMEM>>>(trunk, ln_t_w, ln_t_b, B);
    k_bn<<<1, 80>>>(bn_w, bn_b, B, nblk1);
    k2<<<K2_GRID, 256, SM_TOTAL>>>(node_emb, ln_n_w, ln_n_b, road_pairs, tile_nodes,
                                   sett2_w, sett2_b, city2_w, city2_b,
                                   road2_w, road2_b, rob2_w, rob2_b, out, B);
    k3<<<K3_GRID, 128>>>(gfc2_w, gfc2_b, out, B);
}

// round 8
// speedup vs baseline: 1.4500x; 1.0114x over previous
#include <cuda_runtime.h>
#include <cuda_fp16.h>
#include <cstdint>
#include <cstddef>

// ---------------------------------------------------------------------------
// SmallSpatialPolicyHead — R7 + (k2: non-volatile ldmatrix for W frags) +
// (k3: 8-row batching).
// ---------------------------------------------------------------------------

#define BMAX 16384
#define K2_GRID 296
#define K3_GRID 592

__device__ float d_tb[208];
__device__ __half d_Wh[160 * 48];    // k2 node proj hi  [n][k]
__device__ __half d_Wl[160 * 48];    // k2 node proj lo
__device__ __half d_Wth[208 * 80];   // k1 trunk proj hi [o][k]
__device__ __half d_Wtl[208 * 80];   // k1 trunk proj lo
__device__ float d_tproj[(size_t)BMAX * 128];
__device__ float d_h[(size_t)BMAX * 80];
__device__ float d_partial[296 * 160];
__device__ float d_bnscale[80];
__device__ float d_bnshift[80];

// ---- k2 smem byte offsets (R4 layout) ----
#define SM_XP    0             // xs 108x52 f (overlay) / P_s 108x97 f
#define SM_AH    42336         // 128x56 fp16 = 14336
#define SM_AL    56672
#define SM_WH    71008         // 160x56 fp16 = 17920
#define SM_WL    88928
#define WLOFF    17920
#define SM_TPROJ 106848        // 256 f
#define SM_W2    107872        // 96 f
#define SM_ROB2  108256        // 160 f
#define SM_B2    108896        // 8 f
#define SM_LNW   108928        // 48 f
#define SM_LNB   109120        // 48 f
#define SM_MU    109312        // 108 f
#define SM_IS    109744        // 108 f
#define SM_RP    110176        // 144 i
#define SM_TI    110752        // 114 i
#define SM_TOTAL 111208

// ---- k1 smem byte offsets ----
#define X1_XS    0             // 128x84 f = 43008 (reused as hs)
#define X1_AH    43008         // 128x88 fp16 = 22528
#define X1_AL    65536
#define X1_WH    88064         // 208x88 fp16 = 36608
#define X1_WL    124672
#define W1OFF    36608
#define X1_TB    161280        // 208 f
#define X1_LNW   162112        // 80 f
#define X1_LNB   162432        // 80 f
#define K1_SMEM  162752

__device__ __forceinline__ uint32_t smem_u32(const void* p) {
    uint32_t a;
    asm("{ .reg .u64 t; cvta.to.shared.u64 t, %1; cvt.u32.u64 %0, t; }" : "=r"(a) : "l"(p));
    return a;
}
__device__ __forceinline__ void cp16(uint32_t dst, const void* src) {
    asm volatile("cp.async.cg.shared.global [%0], [%1], 16;" :: "r"(dst), "l"(src));
}
#define CP_COMMIT_WAIT() do { \
    asm volatile("cp.async.commit_group;" ::: "memory"); \
    asm volatile("cp.async.wait_group 0;" ::: "memory"); } while (0)

// volatile variants (k1)
#define LDSM_X4(r0,r1,r2,r3,addr) \
    asm volatile("ldmatrix.sync.aligned.m8n8.x4.shared.b16 {%0,%1,%2,%3}, [%4];" \
        : "=r"(r0),"=r"(r1),"=r"(r2),"=r"(r3) : "r"(addr))
#define LDSM_X2(r0,r1,addr) \
    asm volatile("ldmatrix.sync.aligned.m8n8.x2.shared.b16 {%0,%1}, [%2];" \
        : "=r"(r0),"=r"(r1) : "r"(addr))
// NON-volatile variants (k2 W frags: W tile is immutable after init, so the
// compiler may hoist/reorder these freely across the MMA loop)
#define LDSM_X4_NV(r0,r1,r2,r3,addr) \
    asm("ldmatrix.sync.aligned.m8n8.x4.shared.b16 {%0,%1,%2,%3}, [%4];" \
        : "=r"(r0),"=r"(r1),"=r"(r2),"=r"(r3) : "r"(addr))
#define LDSM_X2_NV(r0,r1,addr) \
    asm("ldmatrix.sync.aligned.m8n8.x2.shared.b16 {%0,%1}, [%2];" \
        : "=r"(r0),"=r"(r1) : "r"(addr))

__device__ __forceinline__ void mma16816(float* d, const uint32_t* a, uint32_t b0, uint32_t b1) {
    asm volatile(
        "mma.sync.aligned.m16n8k16.row.col.f32.f16.f16.f32 "
        "{%0,%1,%2,%3},{%4,%5,%6,%7},{%8,%9},{%0,%1,%2,%3};"
        : "+f"(d[0]), "+f"(d[1]), "+f"(d[2]), "+f"(d[3])
        : "r"(a[0]), "r"(a[1]), "r"(a[2]), "r"(a[3]), "r"(b0), "r"(b1));
}

__device__ __forceinline__ float mishf(float x) {
    float u = __expf(fminf(x, 15.f));
    float d = __fmaf_rn(u, u + 2.f, 2.f);
    return x - __fdividef(2.f * x, d);
}
__device__ __forceinline__ float warp_sum(float v) {
    #pragma unroll
    for (int o = 16; o; o >>= 1) v += __shfl_xor_sync(0xffffffffu, v, o);
    return v;
}

// ------------------------------ prep ------------------------------
__global__ void k_prep(const float* __restrict__ sett1_w, const float* __restrict__ city1_w,
                       const float* __restrict__ road1_w, const float* __restrict__ rob1_w,
                       const float* __restrict__ gfc1_w,
                       const float* __restrict__ sett1_b, const float* __restrict__ city1_b,
                       const float* __restrict__ road1_b, const float* __restrict__ rob1_b,
                       const float* __restrict__ gfc1_b) {
    int i = blockIdx.x * blockDim.x + threadIdx.x;
    if (i < 160 * 48) {
        int j = i / 48, k = i % 48;
        float v;
        if (j < 32)       v = sett1_w[j * 128 + 80 + k];
        else if (j < 64)  v = city1_w[(j - 32) * 128 + 80 + k];
        else if (j < 96)  v = road1_w[(j - 64) * 176 + 80 + k];
        else if (j < 128) v = road1_w[(j - 96) * 176 + 128 + k];
        else              v = rob1_w[(j - 128) * 128 + 80 + k];
        __half h = __float2half(v);
        d_Wh[i] = h;
        d_Wl[i] = __float2half(v - __half2float(h));
    }
    if (i < 208 * 80) {
        int o = i / 80, k = i % 80;
        float v;
        if (o < 32)       v = sett1_w[o * 128 + k];
        else if (o < 64)  v = city1_w[(o - 32) * 128 + k];
        else if (o < 96)  v = road1_w[(o - 64) * 176 + k];
        else if (o < 128) v = rob1_w[(o - 96) * 128 + k];
        else              v = gfc1_w[(o - 128) * 80 + k];
        __half h = __float2half(v);
        d_Wth[i] = h;
        d_Wtl[i] = __float2half(v - __half2float(h));
    }
    if (i < 208) {
        float v;
        if (i < 32)       v = sett1_b[i];
        else if (i < 64)  v = city1_b[i - 32];
        else if (i < 96)  v = road1_b[i - 64];
        else if (i < 128) v = rob1_b[i - 96];
        else              v = gfc1_b[i - 128];
        d_tb[i] = v;
    }
}

// ------------------------------ K1: HMMA trunk kernel (unchanged, proven) ------------------------------
__global__ __launch_bounds__(512, 1) void k1(const float* __restrict__ trunk,
                                             const float* __restrict__ ln_t_w,
                                             const float* __restrict__ ln_t_b, int B) {
    extern __shared__ char smem[];
    const uint32_t sbase = smem_u32(smem);
    const int tid = threadIdx.x, wid = tid >> 5, lane = tid & 31;

    float* xs  = (float*)(smem + X1_XS);
    float* hs  = (float*)(smem + X1_XS);
    float* tb_s = (float*)(smem + X1_TB);
    float* lnw = (float*)(smem + X1_LNW);
    float* lnb = (float*)(smem + X1_LNB);

    for (int i = tid; i < 208 * 80; i += 512) {
        int o = i / 80, k = i % 80;
        *(__half*)(smem + X1_WH + (o * 88 + k) * 2) = d_Wth[i];
        *(__half*)(smem + X1_WL + (o * 88 + k) * 2) = d_Wtl[i];
    }
    for (int i = tid; i < 208; i += 512) tb_s[i] = d_tb[i];
    if (tid < 80) { lnw[tid] = ln_t_w[tid]; lnb[tid] = ln_t_b[tid]; }

    const int rows_valid = min(128, B - (int)blockIdx.x * 128);

    {
        const float4* tr4 = (const float4*)trunk;
        size_t base4 = (size_t)blockIdx.x * 2560;
        #pragma unroll
        for (int q = 0; q < 5; q++) {
            int il = tid + q * 512;
            int row = il / 20, c = il % 20;
            if (row < rows_valid)
                cp16(sbase + X1_XS + (uint32_t)((row * 84 + 4 * c) * 4), tr4 + base4 + il);
        }
        CP_COMMIT_WAIT();
    }
    __syncthreads();

    if (tid < 256) {
        const int r = tid >> 1, h = tid & 1;
        float4 v[10];
        if (r < rows_valid) {
            const float4* xr = (const float4*)(xs + r * 84 + h * 40);
            #pragma unroll
            for (int j = 0; j < 10; j++) v[j] = xr[j];
        } else {
            #pragma unroll
            for (int j = 0; j < 10; j++) v[j] = make_float4(0.f, 0.f, 0.f, 0.f);
        }
        float s = 0.f, q = 0.f;
        #pragma unroll
        for (int j = 0; j < 10; j++) {
            s += v[j].x + v[j].y + v[j].z + v[j].w;
            q += v[j].x * v[j].x + v[j].y * v[j].y + v[j].z * v[j].z + v[j].w * v[j].w;
        }
        s += __shfl_xor_sync(0xffffffffu, s, 1);
        q += __shfl_xor_sync(0xffffffffu, q, 1);
        float mu = s * (1.f / 80.f);
        float is = rsqrtf(q * (1.f / 80.f) - mu * mu + 1e-5f);
        char* dh = smem + X1_AH + (r * 88 + h * 40) * 2;
        char* dl = dh + (X1_AL - X1_AH);
        const float4* lw4 = (const float4*)(lnw + h * 40);
        const float4* lb4 = (const float4*)(lnb + h * 40);
        #pragma unroll
        for (int j = 0; j < 10; j++) {
            float4 w = lw4[j], b = lb4[j];
            float a0 = (v[j].x - mu) * is * w.x + b.x;
            float a1 = (v[j].y - mu) * is * w.y + b.y;
            float a2 = (v[j].z - mu) * is * w.z + b.z;
            float a3 = (v[j].w - mu) * is * w.w + b.w;
            if (r >= rows_valid) { a0 = a1 = a2 = a3 = 0.f; }
            __half2 h01 = __floats2half2_rn(a0, a1), h23 = __floats2half2_rn(a2, a3);
            __half2 l01 = __floats2half2_rn(a0 - __low2float(h01), a1 - __high2float(h01));
            __half2 l23 = __floats2half2_rn(a2 - __low2float(h23), a3 - __high2float(h23));
            uint2 uh; uh.x = *(uint32_t*)&h01; uh.y = *(uint32_t*)&h23;
            uint2 ul; ul.x = *(uint32_t*)&l01; ul.y = *(uint32_t*)&l23;
            *(uint2*)(dh + j * 8) = uh;
            *(uint2*)(dl + j * 8) = ul;
        }
    }
    __syncthreads();

    {
        const int mt = wid & 7, nh = wid >> 3;
        const int g = lane >> 2, k0 = (lane & 3) * 2;
        const uint32_t abase = sbase + X1_AH +
            (uint32_t)((mt * 16 + (lane & 15)) * 176 + (lane >> 4) * 16);
        uint32_t ah[5][4];
        #pragma unroll
        for (int ks = 0; ks < 5; ks++)
            LDSM_X4(ah[ks][0], ah[ks][1], ah[ks][2], ah[ks][3], abase + ks * 32);

        uint32_t wx4 = sbase + X1_WH +
            (uint32_t)((lane & 7) * 176 + (lane >> 3) * 16) + (uint32_t)(nh * 13 * 1408);
        uint32_t wx2 = sbase + X1_WH +
            (uint32_t)((lane & 7) * 176 + ((lane >> 3) & 1) * 16 + 128) + (uint32_t)(nh * 13 * 1408);

        #pragma unroll
        for (int ni = 0; ni < 13; ni++) {
            const int nt = nh * 13 + ni;
            uint32_t bhA[4], bhB[4], bh2[2], blA[4], blB[4], bl2[2];
            LDSM_X4(bhA[0], bhA[1], bhA[2], bhA[3], wx4);
            LDSM_X4(bhB[0], bhB[1], bhB[2], bhB[3], wx4 + 64);
            LDSM_X2(bh2[0], bh2[1], wx2);
            LDSM_X4(blA[0], blA[1], blA[2], blA[3], wx4 + W1OFF);
            LDSM_X4(blB[0], blB[1], blB[2], blB[3], wx4 + 64 + W1OFF);
            LDSM_X2(bl2[0], bl2[1], wx2 + W1OFF);

            float acc[4] = {0.f, 0.f, 0.f, 0.f};
            mma16816(acc, ah[0], bhA[0], bhA[1]);
            mma16816(acc, ah[1], bhA[2], bhA[3]);
            mma16816(acc, ah[2], bhB[0], bhB[1]);
            mma16816(acc, ah[3], bhB[2], bhB[3]);
            mma16816(acc, ah[4], bh2[0], bh2[1]);
            mma16816(acc, ah[0], blA[0], blA[1]);
            mma16816(acc, ah[1], blA[2], blA[3]);
            mma16816(acc, ah[2], blB[0], blB[1]);
            mma16816(acc, ah[3], blB[2], blB[3]);
            mma16816(acc, ah[4], bl2[0], bl2[1]);
            {
                uint32_t al[4];
                const uint32_t albase = abase + (X1_AL - X1_AH);
                LDSM_X4(al[0], al[1], al[2], al[3], albase);
                mma16816(acc, al, bhA[0], bhA[1]);
                LDSM_X4(al[0], al[1], al[2], al[3], albase + 32);
                mma16816(acc, al, bhA[2], bhA[3]);
                LDSM_X4(al[0], al[1], al[2], al[3], albase + 64);
                mma16816(acc, al, bhB[0], bhB[1]);
                LDSM_X4(al[0], al[1], al[2], al[3], albase + 96);
                mma16816(acc, al, bhB[2], bhB[3]);
                LDSM_X4(al[0], al[1], al[2], al[3], albase + 128);
                mma16816(acc, al, bh2[0], bh2[1]);
            }
            wx4 += 1408; wx2 += 1408;

            const int col = nt * 8 + k0;
            const int row0 = mt * 16 + g, row1 = row0 + 8;
            if (col < 128) {
                float b0 = tb_s[col], b1 = tb_s[col + 1];
                if (row0 < rows_valid) {
                    size_t o = (size_t)((size_t)blockIdx.x * 128 + row0) * 128 + col;
                    d_tproj[o] = acc[0] + b0; d_tproj[o + 1] = acc[1] + b1;
                }
                if (row1 < rows_valid) {
                    size_t o = (size_t)((size_t)blockIdx.x * 128 + row1) * 128 + col;
                    d_tproj[o] = acc[2] + b0; d_tproj[o + 1] = acc[3] + b1;
                }
            } else {
                const int ch = col - 128;
                hs[row0 * 84 + ch] = acc[0]; hs[row0 * 84 + ch + 1] = acc[1];
                hs[row1 * 84 + ch] = acc[2]; hs[row1 * 84 + ch + 1] = acc[3];
                if (row0 < rows_valid) {
                    size_t o = (size_t)((size_t)blockIdx.x * 128 + row0) * 80 + ch;
                    d_h[o] = acc[0]; d_h[o + 1] = acc[1];
                }
                if (row1 < rows_valid) {
                    size_t o = (size_t)((size_t)blockIdx.x * 128 + row1) * 80 + ch;
                    d_h[o] = acc[2]; d_h[o + 1] = acc[3];
                }
            }
        }
    }
    __syncthreads();

    if (tid < 80) {
        float s1 = 0.f, s2 = 0.f;
        for (int r = 0; r < rows_valid; r++) {
            float v = hs[r * 84 + tid];
            s1 += v; s2 += v * v;
        }
        d_partial[blockIdx.x * 160 + tid] = s1;
        d_partial[blockIdx.x * 160 + 80 + tid] = s2;
    }
}

// ------------------------------ BN finalize ------------------------------
__global__ void k_bn(const float* __restrict__ bn_w, const float* __restrict__ bn_b,
                     int B, int nblk) {
    int t = threadIdx.x;
    if (t >= 80) return;
    float S1 = 0.f, S2 = 0.f;
    for (int blk = 0; blk < nblk; blk++) {
        S1 += d_partial[blk * 160 + t];
        S2 += d_partial[blk * 160 + 80 + t];
    }
    float invB = 1.f / (float)B;
    float mu = S1 * invB;
    float var = S2 * invB - mu * mu;
    float sc = bn_w[t] * rsqrtf(var + 1e-5f);
    d_bnscale[t] = sc;
    d_bnshift[t] = bn_b[t] - mu * sc;
}

// ------------------------------ K2: HMMA fused node kernel ------------------------------
__global__ __launch_bounds__(256, 2) void k2(const float* __restrict__ node_emb,
                                             const float* __restrict__ ln_n_w,
                                             const float* __restrict__ ln_n_b,
                                             const int* __restrict__ road_pairs,
                                             const int* __restrict__ tile_nodes,
                                             const float* __restrict__ sett2_w, const float* __restrict__ sett2_b,
                                             const float* __restrict__ city2_w, const float* __restrict__ city2_b,
                                             const float* __restrict__ road2_w, const float* __restrict__ road2_b,
                                             const float* __restrict__ rob2_w, const float* __restrict__ rob2_b,
                                             float* __restrict__ out, int B) {
    extern __shared__ char smem[];
    const uint32_t sbase = smem_u32(smem);
    const int tid = threadIdx.x, wid = tid >> 5, lane = tid & 31;

    float* xs      = (float*)(smem + SM_XP);   // rows x 52 (overlay)
    float* P_s     = (float*)(smem + SM_XP);   // rows x 97
    float* tproj_s = (float*)(smem + SM_TPROJ);
    float* w2_s    = (float*)(smem + SM_W2);
    float* rob2_s  = (float*)(smem + SM_ROB2);
    float* b2_s    = (float*)(smem + SM_B2);
    float* lnw     = (float*)(smem + SM_LNW);
    float* lnb     = (float*)(smem + SM_LNB);
    float* mu_s    = (float*)(smem + SM_MU);
    float* is_s    = (float*)(smem + SM_IS);
    int*   rp_s    = (int*)(smem + SM_RP);
    int*   ti_s    = (int*)(smem + SM_TI);

    for (int i = tid; i < 160 * 48; i += 256) {
        int n = i / 48, k = i % 48;
        *(__half*)(smem + SM_WH + (n * 56 + k) * 2) = d_Wh[i];
        *(__half*)(smem + SM_WL + (n * 56 + k) * 2) = d_Wl[i];
    }
    if (tid < 48) { lnw[tid] = ln_n_w[tid]; lnb[tid] = ln_n_b[tid]; }
    if (tid < 32) { w2_s[tid] = sett2_w[tid]; w2_s[32 + tid] = city2_w[tid]; w2_s[64 + tid] = road2_w[tid]; }
    if (tid < 160) rob2_s[tid] = rob2_w[tid];
    if (tid == 0) { b2_s[0] = sett2_b[0]; b2_s[1] = city2_b[0]; b2_s[2] = road2_b[0]; }
    if (tid < 5) b2_s[3 + tid] = rob2_b[tid];
    if (tid < 144) rp_s[tid] = road_pairs[tid];
    if (tid < 114) ti_s[tid] = tile_nodes[tid];

    const int g = lane >> 2;
    const int k0 = (lane & 3) * 2;
    const int mrow = (wid & 3) * 32;
    const int nbase = (wid >> 2) * 10;

    int rown[4]; const float* tpp[4];
    #pragma unroll
    for (int s = 0; s < 4; s++) {
        rown[s] = mrow + 16 * (s >> 1) + 8 * (s & 1) + g;
        tpp[s] = tproj_s + ((rown[s] >= 54) ? 128 : 0);
    }

    // W-frag ldmatrix base addresses (W tile immutable after init)
    const uint32_t wx4base = sbase + SM_WH +
        (uint32_t)((lane & 7) * 112 + (lane >> 3) * 16) + (uint32_t)(nbase * 896);
    const uint32_t wx2base = sbase + SM_WH +
        (uint32_t)((lane & 7) * 112 + ((lane >> 3) & 1) * 16 + 64) + (uint32_t)(nbase * 896);

    const long npairs = ((long)B + 1) / 2;
    const size_t tot4 = (size_t)B * 648;
    const size_t totp4 = (size_t)B * 32;
    const float4* ne4 = (const float4*)node_emb;
    const float4* tp4 = (const float4*)d_tproj;

    for (long pair = blockIdx.x; pair < npairs; pair += gridDim.x) {
        // ---- stage via cp.async ----
        {
            size_t base4 = (size_t)pair * 1296;
            #pragma unroll
            for (int q = 0; q < 6; q++) {
                int il = tid + q * 256;
                if (il < 1296 && base4 + il < tot4) {
                    int row = il / 12, c = il % 12;
                    cp16(sbase + SM_XP + (uint32_t)((row * 52 + 4 * c) * 4), ne4 + base4 + il);
                }
            }
            if (tid < 64) {
                size_t t4 = (size_t)pair * 64 + tid;
                if (t4 < totp4) cp16(sbase + SM_TPROJ + tid * 16, tp4 + t4);
            }
            CP_COMMIT_WAIT();
        }
        __syncthreads();

        const int nrows = (int)((long)B * 54 - pair * 108 >= 108 ? 108 : (long)B * 54 - pair * 108);

        // ---- LN phase A: thread-per-row sums ----
        if (tid < nrows) {
            const float4* xr = (const float4*)(xs + tid * 52);
            float s = 0.f, q = 0.f;
            #pragma unroll
            for (int j = 0; j < 12; j++) {
                float4 v = xr[j];
                s += v.x + v.y + v.z + v.w;
                q += v.x * v.x + v.y * v.y + v.z * v.z + v.w * v.w;
            }
            float mu = s * (1.f / 48.f);
            mu_s[tid] = mu;
            is_s[tid] = rsqrtf(q * (1.f / 48.f) - mu * mu + 1e-5f);
        }
        __syncthreads();

        // ---- LN phase B: vectorized split into AH/AL ----
        for (int i = tid; i < 2592; i += 256) {
            int r = i / 24, c2 = (i % 24) * 2;
            if (r < nrows) {
                float2 v = *(const float2*)(xs + r * 52 + c2);
                float mu = mu_s[r], is = is_s[r];
                float v0 = (v.x - mu) * is * lnw[c2] + lnb[c2];
                float v1 = (v.y - mu) * is * lnw[c2 + 1] + lnb[c2 + 1];
                __half2 h = __floats2half2_rn(v0, v1);
                __half2 l = __floats2half2_rn(v0 - __low2float(h), v1 - __high2float(h));
                *(__half2*)(smem + SM_AH + (r * 56 + c2) * 2) = h;
                *(__half2*)(smem + SM_AL + (r * 56 + c2) * 2) = l;
            }
        }
        __syncthreads();

        // ---- A fragments (plain LDS; compiler-scheduled) ----
        uint32_t afh[2][3][4], afl[2][3][4];
        #pragma unroll
        for (int t = 0; t < 2; t++) {
            #pragma unroll
            for (int ks = 0; ks < 3; ks++) {
                const char* ba = smem + SM_AH + ((mrow + 16 * t + g) * 56 + k0 + 16 * ks) * 2;
                afh[t][ks][0] = *(const uint32_t*)(ba);
                afh[t][ks][1] = *(const uint32_t*)(ba + 896);
                afh[t][ks][2] = *(const uint32_t*)(ba + 16);
                afh[t][ks][3] = *(const uint32_t*)(ba + 896 + 16);
                const char* bl = ba + (SM_AL - SM_AH);
                afl[t][ks][0] = *(const uint32_t*)(bl);
                afl[t][ks][1] = *(const uint32_t*)(bl + 896);
                afl[t][ks][2] = *(const uint32_t*)(bl + 16);
                afl[t][ks][3] = *(const uint32_t*)(bl + 896 + 16);
            }
        }

        float sacc[4] = {0.f, 0.f, 0.f, 0.f}, cacc[4] = {0.f, 0.f, 0.f, 0.f};

        #pragma unroll
        for (int ni = 0; ni < 10; ni++) {
            const int nt = nbase + ni;
            // W frags via NON-volatile ldmatrix: bh = {k0-7, k8-15, k16-23, k24-31}, bh2 = {k32-39, k40-47}
            uint32_t bh[4], bh2[2], bl[4], bl2[2];
            LDSM_X4_NV(bh[0], bh[1], bh[2], bh[3], wx4base + ni * 896);
            LDSM_X2_NV(bh2[0], bh2[1], wx2base + ni * 896);
            LDSM_X4_NV(bl[0], bl[1], bl[2], bl[3], wx4base + ni * 896 + WLOFF);
            LDSM_X2_NV(bl2[0], bl2[1], wx2base + ni * 896 + WLOFF);

            float acc[2][4] = {{0.f, 0.f, 0.f, 0.f}, {0.f, 0.f, 0.f, 0.f}};
            #pragma unroll
            for (int t = 0; t < 2; t++) {
                mma16816(acc[t], afh[t][0], bh[0], bh[1]);
                mma16816(acc[t], afh[t][1], bh[2], bh[3]);
                mma16816(acc[t], afh[t][2], bh2[0], bh2[1]);
                mma16816(acc[t], afh[t][0], bl[0], bl[1]);
                mma16816(acc[t], afh[t][1], bl[2], bl[3]);
                mma16816(acc[t], afh[t][2], bl2[0], bl2[1]);
                mma16816(acc[t], afl[t][0], bh[0], bh[1]);
                mma16816(acc[t], afl[t][1], bh[2], bh[3]);
                mma16816(acc[t], afl[t][2], bh2[0], bh2[1]);
            }
            const int col = nt * 8 + k0;
            if (nt < 8) {
                float w2a = w2_s[col], w2b = w2_s[col + 1];
                float* dst = (nt < 4) ? sacc : cacc;
                #pragma unroll
                for (int s = 0; s < 4; s++) {
                    float v0 = acc[s >> 1][2 * (s & 1)];
                    float v1 = acc[s >> 1][2 * (s & 1) + 1];
                    dst[s] += mishf(v0 + tpp[s][col]) * w2a + mishf(v1 + tpp[s][col + 1]) * w2b;
                }
            } else {
                #pragma unroll
                for (int s = 0; s < 4; s++) {
                    int r = rown[s];
                    if (r < 108) {
                        float* pr = P_s + r * 97 + (col - 64);
                        pr[0] = acc[s >> 1][2 * (s & 1)];
                        pr[1] = acc[s >> 1][2 * (s & 1) + 1];
                    }
                }
            }
        }

        // sett/city finalize (warps 0-3 cover cols 0:64)
        if (wid < 4) {
            #pragma unroll
            for (int s = 0; s < 4; s++) {
                sacc[s] += __shfl_xor_sync(0xffffffffu, sacc[s], 1);
                sacc[s] += __shfl_xor_sync(0xffffffffu, sacc[s], 2);
                cacc[s] += __shfl_xor_sync(0xffffffffu, cacc[s], 1);
                cacc[s] += __shfl_xor_sync(0xffffffffu, cacc[s], 2);
            }
            if ((lane & 3) == 0) {
                #pragma unroll
                for (int s = 0; s < 4; s++) {
                    int r = rown[s];
                    if (r < nrows) {
                        int bl = (r >= 54) ? 1 : 0;
                        int n = r - 54 * bl;
                        size_t ob = ((size_t)(pair * 2 + bl)) * 397;
                        out[ob + 5 + n]  = sacc[s] + b2_s[0];
                        out[ob + 59 + n] = cacc[s] + b2_s[1];
                    }
                }
            }
        }
        __syncthreads();

        const int nb = (nrows > 54) ? 2 : 1;
        for (int t = wid; t < nb * 72; t += 8) {
            int bl = t / 72, e = t - 72 * bl;
            int sN = rp_s[2 * e], dN = rp_s[2 * e + 1];
            float hv = tproj_s[bl * 128 + 64 + lane]
                     + P_s[(bl * 54 + sN) * 97 + lane]
                     + P_s[(bl * 54 + dN) * 97 + 32 + lane];
            float red = warp_sum(mishf(hv) * w2_s[64 + lane]);
            if (lane == 0) out[((size_t)(pair * 2 + bl)) * 397 + 113 + e] = red + b2_s[2];
        }
        for (int t = wid; t < nb * 19; t += 8) {
            int bl = t / 19, tt = t - 19 * bl;
            float a = 0.f;
            #pragma unroll
            for (int i = 0; i < 6; i++)
                a += P_s[(bl * 54 + ti_s[tt * 6 + i]) * 97 + 64 + lane];
            float m = mishf(tproj_s[bl * 128 + 96 + lane] + a * (1.f / 6.f));
            #pragma unroll
            for (int o = 0; o < 5; o++) {
                float red = warp_sum(m * rob2_s[o * 32 + lane]);
                if (lane == 0)
                    out[((size_t)(pair * 2 + bl)) * 397 + 185 + tt * 5 + o] = red + b2_s[3 + o];
            }
        }
        __syncthreads();   // protect xs/P_s overlay before next staging
    }
}

// ------------------------------ K3: BN + mish + gfc2, 8-row batched ------------------------------
__global__ __launch_bounds__(128) void k3(const float* __restrict__ gfc2_w,
                                          const float* __restrict__ gfc2_b,
                                          float* __restrict__ out, int B) {
    __shared__ __align__(16) float m8[80 * 8];
    __shared__ __align__(16) float Wg[80 * 122];
    __shared__ float bs[122];
    __shared__ float sc[80], sh[80];
    int tid = threadIdx.x;
    for (int i = tid; i < 80 * 122; i += 128) {
        int k = i / 122, t = i % 122;
        int r = (t < 5) ? t : (275 + t);
        Wg[i] = gfc2_w[r * 80 + k];
    }
    if (tid < 122) { int r = (tid < 5) ? tid : (275 + tid); bs[tid] = gfc2_b[r]; }
    if (tid < 80) { sc[tid] = d_bnscale[tid]; sh[tid] = d_bnshift[tid]; }
    __syncthreads();
    int nq = (B + 7) >> 3;
    for (int qb = blockIdx.x; qb < nq; qb += gridDim.x) {
        if (tid < 80) {
            #pragma unroll
            for (int rb = 0; rb < 8; rb++) {
                int b = qb * 8 + rb;
                float v = (b < B) ? d_h[(size_t)b * 80 + tid] : 0.f;
                m8[tid * 8 + rb] = mishf(v * sc[tid] + sh[tid]);
            }
        }
        __syncthreads();
        if (tid < 122) {
            float a[8];
            #pragma unroll
            for (int rb = 0; rb < 8; rb++) a[rb] = bs[tid];
            for (int k = 0; k < 80; k++) {
                float4 mA = *(const float4*)(m8 + k * 8);
                float4 mB = *(const float4*)(m8 + k * 8 + 4);
                float w = Wg[k * 122 + tid];
                a[0] += mA.x * w; a[1] += mA.y * w; a[2] += mA.z * w; a[3] += mA.w * w;
                a[4] += mB.x * w; a[5] += mB.y * w; a[6] += mB.z * w; a[7] += mB.w * w;
            }
            int col = (tid < 5) ? tid : (275 + tid);
            #pragma unroll
            for (int rb = 0; rb < 8; rb++) {
                int b = qb * 8 + rb;
                if (b < B) out[(size_t)b * 397 + col] = a[rb];
            }
        }
        __syncthreads();
    }
}

// ------------------------------ launch ------------------------------
extern "C" void kernel_launch(void* const* d_in, const int* in_sizes, int n_in,
                              void* d_out, int out_size) {
    const float* trunk      = (const float*)d_in[0];
    const float* node_emb   = (const float*)d_in[1];
    const int*   road_pairs = (const int*)d_in[2];
    const int*   tile_nodes = (const int*)d_in[3];
    const float* ln_t_w = (const float*)d_in[4];
    const float* ln_t_b = (const float*)d_in[5];
    const float* ln_n_w = (const float*)d_in[6];
    const float* ln_n_b = (const float*)d_in[7];
    const float* gfc1_w = (const float*)d_in[8];
    const float* gfc1_b = (const float*)d_in[9];
    const float* bn_w   = (const float*)d_in[10];
    const float* bn_b   = (const float*)d_in[11];
    const float* gfc2_w = (const float*)d_in[12];
    const float* gfc2_b = (const float*)d_in[13];
    const float* sett1_w = (const float*)d_in[14];
    const float* sett1_b = (const float*)d_in[15];
    const float* sett2_w = (const float*)d_in[16];
    const float* sett2_b = (const float*)d_in[17];
    const float* city1_w = (const float*)d_in[18];
    const float* city1_b = (const float*)d_in[19];
    const float* city2_w = (const float*)d_in[20];
    const float* city2_b = (const float*)d_in[21];
    const float* road1_w = (const float*)d_in[22];
    const float* road1_b = (const float*)d_in[23];
    const float* road2_w = (const float*)d_in[24];
    const float* road2_b = (const float*)d_in[25];
    const float* rob1_w = (const float*)d_in[26];
    const float* rob1_b = (const float*)d_in[27];
    const float* rob2_w = (const float*)d_in[28];
    const float* rob2_b = (const float*)d_in[29];

    int B = in_sizes[0] / 80;
    if (B > BMAX) B = BMAX;
    float* out = (float*)d_out;
    int nblk1 = (B + 127) / 128;

    cudaFuncSetAttribute(k1, cudaFuncAttributeMaxDynamicSharedMemorySize, K1_SMEM);
    cudaFuncSetAttribute(k2, cudaFuncAttributeMaxDynamicSharedMemorySize, SM_TOTAL);

    k_prep<<<(208 * 80 + 255) / 256, 256>>>(sett1_w, city1_w, road1_w, rob1_w, gfc1_w,
                                            sett1_b, city1_b, road1_b, rob1_b, gfc1_b);
    k1<<<nblk1, 512, K1_SMEM>>>(trunk, ln_t_w, ln_t_b, B);
    k_bn<<<1, 80>>>(bn_w, bn_b, B, nblk1);
    k2<<<K2_GRID, 256, SM_TOTAL>>>(node_emb, ln_n_w, ln_n_b, road_pairs, tile_nodes,
                                   sett2_w, sett2_b, city2_w, city2_b,
                                   road2_w, road2_b, rob2_w, rob2_b, out, B);
    k3<<<K3_GRID, 128>>>(gfc2_w, gfc2_b, out, B);
}

// round 9
// speedup vs baseline: 1.6799x; 1.1586x over previous
#include <cuda_runtime.h>
#include <cuda_fp16.h>
#include <cstdint>
#include <cstddef>

// ---------------------------------------------------------------------------
// SmallSpatialPolicyHead — R8 + k2: no-staging LN (gmem direct), balanced
// sett/city epilogue across all 8 warps, 8-lane-group road heads.
// ---------------------------------------------------------------------------

#define BMAX 16384
#define K2_GRID 296
#define K3_GRID 592

__device__ float d_tb[208];
__device__ __half d_Wh[160 * 48];    // k2 node proj hi  [n][k]
__device__ __half d_Wl[160 * 48];    // k2 node proj lo
__device__ __half d_Wth[208 * 80];   // k1 trunk proj hi [o][k]
__device__ __half d_Wtl[208 * 80];   // k1 trunk proj lo
__device__ float d_tproj[(size_t)BMAX * 128];
__device__ float d_h[(size_t)BMAX * 80];
__device__ float d_partial[296 * 160];
__device__ float d_bnscale[80];
__device__ float d_bnshift[80];

// ---- k2 smem byte offsets ----
#define SM_XP    0             // P_s 108x97 f = 41904 (no more xs overlay)
#define SM_AH    42336         // 128x56 fp16 = 14336
#define SM_AL    56672
#define SM_WH    71008         // 160x56 fp16 = 17920
#define SM_WL    88928
#define WLOFF    17920
#define SM_TPROJ 106848        // 256 f
#define SM_W2    107872        // 96 f
#define SM_ROB2  108256        // 160 f
#define SM_B2    108896        // 8 f
#define SM_LNW   108928        // 48 f
#define SM_LNB   109120        // 48 f
#define SM_MU    109312        // 108 f
#define SM_IS    109744        // 108 f
#define SM_RP    110176        // 144 i
#define SM_TI    110752        // 114 i
#define SM_TOTAL 111208

// ---- k1 smem byte offsets ----
#define X1_XS    0             // 128x84 f = 43008 (reused as hs)
#define X1_AH    43008         // 128x88 fp16 = 22528
#define X1_AL    65536
#define X1_WH    88064         // 208x88 fp16 = 36608
#define X1_WL    124672
#define W1OFF    36608
#define X1_TB    161280        // 208 f
#define X1_LNW   162112        // 80 f
#define X1_LNB   162432        // 80 f
#define K1_SMEM  162752

__device__ __forceinline__ uint32_t smem_u32(const void* p) {
    uint32_t a;
    asm("{ .reg .u64 t; cvta.to.shared.u64 t, %1; cvt.u32.u64 %0, t; }" : "=r"(a) : "l"(p));
    return a;
}
__device__ __forceinline__ void cp16(uint32_t dst, const void* src) {
    asm volatile("cp.async.cg.shared.global [%0], [%1], 16;" :: "r"(dst), "l"(src));
}
#define CP_COMMIT_WAIT() do { \
    asm volatile("cp.async.commit_group;" ::: "memory"); \
    asm volatile("cp.async.wait_group 0;" ::: "memory"); } while (0)

#define LDSM_X4(r0,r1,r2,r3,addr) \
    asm volatile("ldmatrix.sync.aligned.m8n8.x4.shared.b16 {%0,%1,%2,%3}, [%4];" \
        : "=r"(r0),"=r"(r1),"=r"(r2),"=r"(r3) : "r"(addr))
#define LDSM_X2(r0,r1,addr) \
    asm volatile("ldmatrix.sync.aligned.m8n8.x2.shared.b16 {%0,%1}, [%2];" \
        : "=r"(r0),"=r"(r1) : "r"(addr))
#define LDSM_X4_NV(r0,r1,r2,r3,addr) \
    asm("ldmatrix.sync.aligned.m8n8.x4.shared.b16 {%0,%1,%2,%3}, [%4];" \
        : "=r"(r0),"=r"(r1),"=r"(r2),"=r"(r3) : "r"(addr))
#define LDSM_X2_NV(r0,r1,addr) \
    asm("ldmatrix.sync.aligned.m8n8.x2.shared.b16 {%0,%1}, [%2];" \
        : "=r"(r0),"=r"(r1) : "r"(addr))

__device__ __forceinline__ void mma16816(float* d, const uint32_t* a, uint32_t b0, uint32_t b1) {
    asm volatile(
        "mma.sync.aligned.m16n8k16.row.col.f32.f16.f16.f32 "
        "{%0,%1,%2,%3},{%4,%5,%6,%7},{%8,%9},{%0,%1,%2,%3};"
        : "+f"(d[0]), "+f"(d[1]), "+f"(d[2]), "+f"(d[3])
        : "r"(a[0]), "r"(a[1]), "r"(a[2]), "r"(a[3]), "r"(b0), "r"(b1));
}

__device__ __forceinline__ float mishf(float x) {
    float u = __expf(fminf(x, 15.f));
    float d = __fmaf_rn(u, u + 2.f, 2.f);
    return x - __fdividef(2.f * x, d);
}
__device__ __forceinline__ float warp_sum(float v) {
    #pragma unroll
    for (int o = 16; o; o >>= 1) v += __shfl_xor_sync(0xffffffffu, v, o);
    return v;
}

// ------------------------------ prep ------------------------------
__global__ void k_prep(const float* __restrict__ sett1_w, const float* __restrict__ city1_w,
                       const float* __restrict__ road1_w, const float* __restrict__ rob1_w,
                       const float* __restrict__ gfc1_w,
                       const float* __restrict__ sett1_b, const float* __restrict__ city1_b,
                       const float* __restrict__ road1_b, const float* __restrict__ rob1_b,
                       const float* __restrict__ gfc1_b) {
    int i = blockIdx.x * blockDim.x + threadIdx.x;
    if (i < 160 * 48) {
        int j = i / 48, k = i % 48;
        float v;
        if (j < 32)       v = sett1_w[j * 128 + 80 + k];
        else if (j < 64)  v = city1_w[(j - 32) * 128 + 80 + k];
        else if (j < 96)  v = road1_w[(j - 64) * 176 + 80 + k];
        else if (j < 128) v = road1_w[(j - 96) * 176 + 128 + k];
        else              v = rob1_w[(j - 128) * 128 + 80 + k];
        __half h = __float2half(v);
        d_Wh[i] = h;
        d_Wl[i] = __float2half(v - __half2float(h));
    }
    if (i < 208 * 80) {
        int o = i / 80, k = i % 80;
        float v;
        if (o < 32)       v = sett1_w[o * 128 + k];
        else if (o < 64)  v = city1_w[(o - 32) * 128 + k];
        else if (o < 96)  v = road1_w[(o - 64) * 176 + k];
        else if (o < 128) v = rob1_w[(o - 96) * 128 + k];
        else              v = gfc1_w[(o - 128) * 80 + k];
        __half h = __float2half(v);
        d_Wth[i] = h;
        d_Wtl[i] = __float2half(v - __half2float(h));
    }
    if (i < 208) {
        float v;
        if (i < 32)       v = sett1_b[i];
        else if (i < 64)  v = city1_b[i - 32];
        else if (i < 96)  v = road1_b[i - 64];
        else if (i < 128) v = rob1_b[i - 96];
        else              v = gfc1_b[i - 128];
        d_tb[i] = v;
    }
}

// ------------------------------ K1: HMMA trunk kernel (unchanged, proven) ------------------------------
__global__ __launch_bounds__(512, 1) void k1(const float* __restrict__ trunk,
                                             const float* __restrict__ ln_t_w,
                                             const float* __restrict__ ln_t_b, int B) {
    extern __shared__ char smem[];
    const uint32_t sbase = smem_u32(smem);
    const int tid = threadIdx.x, wid = tid >> 5, lane = tid & 31;

    float* xs  = (float*)(smem + X1_XS);
    float* hs  = (float*)(smem + X1_XS);
    float* tb_s = (float*)(smem + X1_TB);
    float* lnw = (float*)(smem + X1_LNW);
    float* lnb = (float*)(smem + X1_LNB);

    for (int i = tid; i < 208 * 80; i += 512) {
        int o = i / 80, k = i % 80;
        *(__half*)(smem + X1_WH + (o * 88 + k) * 2) = d_Wth[i];
        *(__half*)(smem + X1_WL + (o * 88 + k) * 2) = d_Wtl[i];
    }
    for (int i = tid; i < 208; i += 512) tb_s[i] = d_tb[i];
    if (tid < 80) { lnw[tid] = ln_t_w[tid]; lnb[tid] = ln_t_b[tid]; }

    const int rows_valid = min(128, B - (int)blockIdx.x * 128);

    {
        const float4* tr4 = (const float4*)trunk;
        size_t base4 = (size_t)blockIdx.x * 2560;
        #pragma unroll
        for (int q = 0; q < 5; q++) {
            int il = tid + q * 512;
            int row = il / 20, c = il % 20;
            if (row < rows_valid)
                cp16(sbase + X1_XS + (uint32_t)((row * 84 + 4 * c) * 4), tr4 + base4 + il);
        }
        CP_COMMIT_WAIT();
    }
    __syncthreads();

    if (tid < 256) {
        const int r = tid >> 1, h = tid & 1;
        float4 v[10];
        if (r < rows_valid) {
            const float4* xr = (const float4*)(xs + r * 84 + h * 40);
            #pragma unroll
            for (int j = 0; j < 10; j++) v[j] = xr[j];
        } else {
            #pragma unroll
            for (int j = 0; j < 10; j++) v[j] = make_float4(0.f, 0.f, 0.f, 0.f);
        }
        float s = 0.f, q = 0.f;
        #pragma unroll
        for (int j = 0; j < 10; j++) {
            s += v[j].x + v[j].y + v[j].z + v[j].w;
            q += v[j].x * v[j].x + v[j].y * v[j].y + v[j].z * v[j].z + v[j].w * v[j].w;
        }
        s += __shfl_xor_sync(0xffffffffu, s, 1);
        q += __shfl_xor_sync(0xffffffffu, q, 1);
        float mu = s * (1.f / 80.f);
        float is = rsqrtf(q * (1.f / 80.f) - mu * mu + 1e-5f);
        char* dh = smem + X1_AH + (r * 88 + h * 40) * 2;
        char* dl = dh + (X1_AL - X1_AH);
        const float4* lw4 = (const float4*)(lnw + h * 40);
        const float4* lb4 = (const float4*)(lnb + h * 40);
        #pragma unroll
        for (int j = 0; j < 10; j++) {
            float4 w = lw4[j], b = lb4[j];
            float a0 = (v[j].x - mu) * is * w.x + b.x;
            float a1 = (v[j].y - mu) * is * w.y + b.y;
            float a2 = (v[j].z - mu) * is * w.z + b.z;
            float a3 = (v[j].w - mu) * is * w.w + b.w;
            if (r >= rows_valid) { a0 = a1 = a2 = a3 = 0.f; }
            __half2 h01 = __floats2half2_rn(a0, a1), h23 = __floats2half2_rn(a2, a3);
            __half2 l01 = __floats2half2_rn(a0 - __low2float(h01), a1 - __high2float(h01));
            __half2 l23 = __floats2half2_rn(a2 - __low2float(h23), a3 - __high2float(h23));
            uint2 uh; uh.x = *(uint32_t*)&h01; uh.y = *(uint32_t*)&h23;
            uint2 ul; ul.x = *(uint32_t*)&l01; ul.y = *(uint32_t*)&l23;
            *(uint2*)(dh + j * 8) = uh;
            *(uint2*)(dl + j * 8) = ul;
        }
    }
    __syncthreads();

    {
        const int mt = wid & 7, nh = wid >> 3;
        const int g = lane >> 2, k0 = (lane & 3) * 2;
        const uint32_t abase = sbase + X1_AH +
            (uint32_t)((mt * 16 + (lane & 15)) * 176 + (lane >> 4) * 16);
        uint32_t ah[5][4];
        #pragma unroll
        for (int ks = 0; ks < 5; ks++)
            LDSM_X4(ah[ks][0], ah[ks][1], ah[ks][2], ah[ks][3], abase + ks * 32);

        uint32_t wx4 = sbase + X1_WH +
            (uint32_t)((lane & 7) * 176 + (lane >> 3) * 16) + (uint32_t)(nh * 13 * 1408);
        uint32_t wx2 = sbase + X1_WH +
            (uint32_t)((lane & 7) * 176 + ((lane >> 3) & 1) * 16 + 128) + (uint32_t)(nh * 13 * 1408);

        #pragma unroll
        for (int ni = 0; ni < 13; ni++) {
            const int nt = nh * 13 + ni;
            uint32_t bhA[4], bhB[4], bh2[2], blA[4], blB[4], bl2[2];
            LDSM_X4(bhA[0], bhA[1], bhA[2], bhA[3], wx4);
            LDSM_X4(bhB[0], bhB[1], bhB[2], bhB[3], wx4 + 64);
            LDSM_X2(bh2[0], bh2[1], wx2);
            LDSM_X4(blA[0], blA[1], blA[2], blA[3], wx4 + W1OFF);
            LDSM_X4(blB[0], blB[1], blB[2], blB[3], wx4 + 64 + W1OFF);
            LDSM_X2(bl2[0], bl2[1], wx2 + W1OFF);

            float acc[4] = {0.f, 0.f, 0.f, 0.f};
            mma16816(acc, ah[0], bhA[0], bhA[1]);
            mma16816(acc, ah[1], bhA[2], bhA[3]);
            mma16816(acc, ah[2], bhB[0], bhB[1]);
            mma16816(acc, ah[3], bhB[2], bhB[3]);
            mma16816(acc, ah[4], bh2[0], bh2[1]);
            mma16816(acc, ah[0], blA[0], blA[1]);
            mma16816(acc, ah[1], blA[2], blA[3]);
            mma16816(acc, ah[2], blB[0], blB[1]);
            mma16816(acc, ah[3], blB[2], blB[3]);
            mma16816(acc, ah[4], bl2[0], bl2[1]);
            {
                uint32_t al[4];
                const uint32_t albase = abase + (X1_AL - X1_AH);
                LDSM_X4(al[0], al[1], al[2], al[3], albase);
                mma16816(acc, al, bhA[0], bhA[1]);
                LDSM_X4(al[0], al[1], al[2], al[3], albase + 32);
                mma16816(acc, al, bhA[2], bhA[3]);
                LDSM_X4(al[0], al[1], al[2], al[3], albase + 64);
                mma16816(acc, al, bhB[0], bhB[1]);
                LDSM_X4(al[0], al[1], al[2], al[3], albase + 96);
                mma16816(acc, al, bhB[2], bhB[3]);
                LDSM_X4(al[0], al[1], al[2], al[3], albase + 128);
                mma16816(acc, al, bh2[0], bh2[1]);
            }
            wx4 += 1408; wx2 += 1408;

            const int col = nt * 8 + k0;
            const int row0 = mt * 16 + g, row1 = row0 + 8;
            if (col < 128) {
                float b0 = tb_s[col], b1 = tb_s[col + 1];
                if (row0 < rows_valid) {
                    size_t o = (size_t)((size_t)blockIdx.x * 128 + row0) * 128 + col;
                    d_tproj[o] = acc[0] + b0; d_tproj[o + 1] = acc[1] + b1;
                }
                if (row1 < rows_valid) {
                    size_t o = (size_t)((size_t)blockIdx.x * 128 + row1) * 128 + col;
                    d_tproj[o] = acc[2] + b0; d_tproj[o + 1] = acc[3] + b1;
                }
            } else {
                const int ch = col - 128;
                hs[row0 * 84 + ch] = acc[0]; hs[row0 * 84 + ch + 1] = acc[1];
                hs[row1 * 84 + ch] = acc[2]; hs[row1 * 84 + ch + 1] = acc[3];
                if (row0 < rows_valid) {
                    size_t o = (size_t)((size_t)blockIdx.x * 128 + row0) * 80 + ch;
                    d_h[o] = acc[0]; d_h[o + 1] = acc[1];
                }
                if (row1 < rows_valid) {
                    size_t o = (size_t)((size_t)blockIdx.x * 128 + row1) * 80 + ch;
                    d_h[o] = acc[2]; d_h[o + 1] = acc[3];
                }
            }
        }
    }
    __syncthreads();

    if (tid < 80) {
        float s1 = 0.f, s2 = 0.f;
        for (int r = 0; r < rows_valid; r++) {
            float v = hs[r * 84 + tid];
            s1 += v; s2 += v * v;
        }
        d_partial[blockIdx.x * 160 + tid] = s1;
        d_partial[blockIdx.x * 160 + 80 + tid] = s2;
    }
}

// ------------------------------ BN finalize ------------------------------
__global__ void k_bn(const float* __restrict__ bn_w, const float* __restrict__ bn_b,
                     int B, int nblk) {
    int t = threadIdx.x;
    if (t >= 80) return;
    float S1 = 0.f, S2 = 0.f;
    for (int blk = 0; blk < nblk; blk++) {
        S1 += d_partial[blk * 160 + t];
        S2 += d_partial[blk * 160 + 80 + t];
    }
    float invB = 1.f / (float)B;
    float mu = S1 * invB;
    float var = S2 * invB - mu * mu;
    float sc = bn_w[t] * rsqrtf(var + 1e-5f);
    d_bnscale[t] = sc;
    d_bnshift[t] = bn_b[t] - mu * sc;
}

// ------------------------------ K2: HMMA fused node kernel ------------------------------
__global__ __launch_bounds__(256, 2) void k2(const float* __restrict__ node_emb,
                                             const float* __restrict__ ln_n_w,
                                             const float* __restrict__ ln_n_b,
                                             const int* __restrict__ road_pairs,
                                             const int* __restrict__ tile_nodes,
                                             const float* __restrict__ sett2_w, const float* __restrict__ sett2_b,
                                             const float* __restrict__ city2_w, const float* __restrict__ city2_b,
                                             const float* __restrict__ road2_w, const float* __restrict__ road2_b,
                                             const float* __restrict__ rob2_w, const float* __restrict__ rob2_b,
                                             float* __restrict__ out, int B) {
    extern __shared__ char smem[];
    const uint32_t sbase = smem_u32(smem);
    const int tid = threadIdx.x, wid = tid >> 5, lane = tid & 31;

    float* P_s     = (float*)(smem + SM_XP);   // rows x 97
    float* tproj_s = (float*)(smem + SM_TPROJ);
    float* w2_s    = (float*)(smem + SM_W2);
    float* rob2_s  = (float*)(smem + SM_ROB2);
    float* b2_s    = (float*)(smem + SM_B2);
    float* lnw     = (float*)(smem + SM_LNW);
    float* lnb     = (float*)(smem + SM_LNB);
    float* mu_s    = (float*)(smem + SM_MU);
    float* is_s    = (float*)(smem + SM_IS);
    int*   rp_s    = (int*)(smem + SM_RP);
    int*   ti_s    = (int*)(smem + SM_TI);

    for (int i = tid; i < 160 * 48; i += 256) {
        int n = i / 48, k = i % 48;
        *(__half*)(smem + SM_WH + (n * 56 + k) * 2) = d_Wh[i];
        *(__half*)(smem + SM_WL + (n * 56 + k) * 2) = d_Wl[i];
    }
    if (tid < 48) { lnw[tid] = ln_n_w[tid]; lnb[tid] = ln_n_b[tid]; }
    if (tid < 32) { w2_s[tid] = sett2_w[tid]; w2_s[32 + tid] = city2_w[tid]; w2_s[64 + tid] = road2_w[tid]; }
    if (tid < 160) rob2_s[tid] = rob2_w[tid];
    if (tid == 0) { b2_s[0] = sett2_b[0]; b2_s[1] = city2_b[0]; b2_s[2] = road2_b[0]; }
    if (tid < 5) b2_s[3 + tid] = rob2_b[tid];
    if (tid < 144) rp_s[tid] = road_pairs[tid];
    if (tid < 114) ti_s[tid] = tile_nodes[tid];

    const int g = lane >> 2;
    const int k0 = (lane & 3) * 2;
    const int mrow = (wid & 3) * 32;
    const int hd = wid >> 2;              // 0 = sett group, 1 = city group

    int rown[4]; const float* tpp[4];
    #pragma unroll
    for (int s = 0; s < 4; s++) {
        rown[s] = mrow + 16 * (s >> 1) + 8 * (s & 1) + g;
        tpp[s] = tproj_s + ((rown[s] >= 54) ? 128 : 0);
    }

    // W-frag ldmatrix base addresses (per-nt offset added in loop)
    const uint32_t wx4base0 = sbase + SM_WH +
        (uint32_t)((lane & 7) * 112 + (lane >> 3) * 16);
    const uint32_t wx2base0 = sbase + SM_WH +
        (uint32_t)((lane & 7) * 112 + ((lane >> 3) & 1) * 16 + 64);

    const long npairs = ((long)B + 1) / 2;
    const size_t totp4 = (size_t)B * 32;
    const float4* tp4 = (const float4*)d_tproj;

    for (long pair = blockIdx.x; pair < npairs; pair += gridDim.x) {
        const int nrows = (int)((long)B * 54 - pair * 108 >= 108 ? 108 : (long)B * 54 - pair * 108);

        // tproj prefetch (1KB)
        if (tid < 64) {
            size_t t4 = (size_t)pair * 64 + tid;
            if (t4 < totp4) cp16(sbase + SM_TPROJ + tid * 16, tp4 + t4);
        }

        // ---- LN phase A: thread-per-row sums, direct from gmem ----
        if (tid < nrows) {
            const float4* xr = (const float4*)(node_emb + ((size_t)pair * 108 + tid) * 48);
            float s = 0.f, q = 0.f;
            #pragma unroll
            for (int j = 0; j < 12; j++) {
                float4 v = xr[j];
                s += v.x + v.y + v.z + v.w;
                q += v.x * v.x + v.y * v.y + v.z * v.z + v.w * v.w;
            }
            float mu = s * (1.f / 48.f);
            mu_s[tid] = mu;
            is_s[tid] = rsqrtf(q * (1.f / 48.f) - mu * mu + 1e-5f);
        }
        CP_COMMIT_WAIT();
        __syncthreads();

        // ---- LN phase B: re-read gmem (L1 hit), split into AH/AL ----
        for (int i = tid; i < 2592; i += 256) {
            int r = i / 24, c2 = (i % 24) * 2;
            if (r < nrows) {
                float2 v = *(const float2*)(node_emb + ((size_t)pair * 108 + r) * 48 + c2);
                float mu = mu_s[r], is = is_s[r];
                float v0 = (v.x - mu) * is * lnw[c2] + lnb[c2];
                float v1 = (v.y - mu) * is * lnw[c2 + 1] + lnb[c2 + 1];
                __half2 h = __floats2half2_rn(v0, v1);
                __half2 l = __floats2half2_rn(v0 - __low2float(h), v1 - __high2float(h));
                *(__half2*)(smem + SM_AH + (r * 56 + c2) * 2) = h;
                *(__half2*)(smem + SM_AL + (r * 56 + c2) * 2) = l;
            }
        }
        __syncthreads();

        // ---- A fragments (plain LDS; compiler-scheduled) ----
        uint32_t afh[2][3][4], afl[2][3][4];
        #pragma unroll
        for (int t = 0; t < 2; t++) {
            #pragma unroll
            for (int ks = 0; ks < 3; ks++) {
                const char* ba = smem + SM_AH + ((mrow + 16 * t + g) * 56 + k0 + 16 * ks) * 2;
                afh[t][ks][0] = *(const uint32_t*)(ba);
                afh[t][ks][1] = *(const uint32_t*)(ba + 896);
                afh[t][ks][2] = *(const uint32_t*)(ba + 16);
                afh[t][ks][3] = *(const uint32_t*)(ba + 896 + 16);
                const char* bl = ba + (SM_AL - SM_AH);
                afl[t][ks][0] = *(const uint32_t*)(bl);
                afl[t][ks][1] = *(const uint32_t*)(bl + 896);
                afl[t][ks][2] = *(const uint32_t*)(bl + 16);
                afl[t][ks][3] = *(const uint32_t*)(bl + 896 + 16);
            }
        }

        float sacc[4] = {0.f, 0.f, 0.f, 0.f};

        // nt map: hd=0 -> {0,1,2,3, 8..13}; hd=1 -> {4,5,6,7, 14..19}
        #pragma unroll
        for (int ni = 0; ni < 10; ni++) {
            const int nt = (ni < 4) ? (4 * hd + ni) : (8 + 6 * hd + (ni - 4));
            uint32_t bh[4], bh2[2], bl[4], bl2[2];
            LDSM_X4_NV(bh[0], bh[1], bh[2], bh[3], wx4base0 + nt * 896);
            LDSM_X2_NV(bh2[0], bh2[1], wx2base0 + nt * 896);
            LDSM_X4_NV(bl[0], bl[1], bl[2], bl[3], wx4base0 + nt * 896 + WLOFF);
            LDSM_X2_NV(bl2[0], bl2[1], wx2base0 + nt * 896 + WLOFF);

            float acc[2][4] = {{0.f, 0.f, 0.f, 0.f}, {0.f, 0.f, 0.f, 0.f}};
            #pragma unroll
            for (int t = 0; t < 2; t++) {
                mma16816(acc[t], afh[t][0], bh[0], bh[1]);
                mma16816(acc[t], afh[t][1], bh[2], bh[3]);
                mma16816(acc[t], afh[t][2], bh2[0], bh2[1]);
                mma16816(acc[t], afh[t][0], bl[0], bl[1]);
                mma16816(acc[t], afh[t][1], bl[2], bl[3]);
                mma16816(acc[t], afh[t][2], bl2[0], bl2[1]);
                mma16816(acc[t], afl[t][0], bh[0], bh[1]);
                mma16816(acc[t], afl[t][1], bh[2], bh[3]);
                mma16816(acc[t], afl[t][2], bh2[0], bh2[1]);
            }
            const int col = nt * 8 + k0;
            if (ni < 4) {
                // sett (hd=0, cols 0:32) or city (hd=1, cols 32:64) partials
                float w2a = w2_s[col], w2b = w2_s[col + 1];
                #pragma unroll
                for (int s = 0; s < 4; s++) {
                    float v0 = acc[s >> 1][2 * (s & 1)];
                    float v1 = acc[s >> 1][2 * (s & 1) + 1];
                    sacc[s] += mishf(v0 + tpp[s][col]) * w2a + mishf(v1 + tpp[s][col + 1]) * w2b;
                }
            } else {
                #pragma unroll
                for (int s = 0; s < 4; s++) {
                    int r = rown[s];
                    if (r < 108) {
                        float* pr = P_s + r * 97 + (col - 64);
                        pr[0] = acc[s >> 1][2 * (s & 1)];
                        pr[1] = acc[s >> 1][2 * (s & 1) + 1];
                    }
                }
            }
        }

        // sett/city finalize: every warp reduces its single head
        {
            #pragma unroll
            for (int s = 0; s < 4; s++) {
                sacc[s] += __shfl_xor_sync(0xffffffffu, sacc[s], 1);
                sacc[s] += __shfl_xor_sync(0xffffffffu, sacc[s], 2);
            }
            if ((lane & 3) == 0) {
                #pragma unroll
                for (int s = 0; s < 4; s++) {
                    int r = rown[s];
                    if (r < nrows) {
                        int bl = (r >= 54) ? 1 : 0;
                        int n = r - 54 * bl;
                        out[((size_t)(pair * 2 + bl)) * 397 + 5 + 54 * hd + n] = sacc[s] + b2_s[hd];
                    }
                }
            }
        }
        __syncthreads();

        const int nb = (nrows > 54) ? 2 : 1;
        // ---- road heads: 4 edges per warp-task, 8-lane groups ----
        {
            const int sub = lane >> 3, c = lane & 7;
            for (int t = wid; t < nb * 18; t += 8) {
                int bl = (t >= 18) ? 1 : 0;
                int tg = t - 18 * bl;
                int e = tg * 4 + sub;
                int sN = rp_s[2 * e], dN = rp_s[2 * e + 1];
                const float* tp = tproj_s + bl * 128 + 64;
                const float* Ps = P_s + (bl * 54 + sN) * 97;
                const float* Pd = P_s + (bl * 54 + dN) * 97 + 32;
                float part = 0.f;
                #pragma unroll
                for (int j = 0; j < 4; j++) {
                    int cj = c + 8 * j;
                    part += mishf(tp[cj] + Ps[cj] + Pd[cj]) * w2_s[64 + cj];
                }
                part += __shfl_xor_sync(0xffffffffu, part, 1);
                part += __shfl_xor_sync(0xffffffffu, part, 2);
                part += __shfl_xor_sync(0xffffffffu, part, 4);
                if (c == 0) out[((size_t)(pair * 2 + bl)) * 397 + 113 + e] = part + b2_s[2];
            }
        }
        // ---- robber heads ----
        for (int t = wid; t < nb * 19; t += 8) {
            int bl = (t >= 19) ? 1 : 0;
            int tt = t - 19 * bl;
            float a = 0.f;
            #pragma unroll
            for (int i = 0; i < 6; i++)
                a += P_s[(bl * 54 + ti_s[tt * 6 + i]) * 97 + 64 + lane];
            float m = mishf(tproj_s[bl * 128 + 96 + lane] + a * (1.f / 6.f));
            #pragma unroll
            for (int o = 0; o < 5; o++) {
                float red = warp_sum(m * rob2_s[o * 32 + lane]);
                if (lane == 0)
                    out[((size_t)(pair * 2 + bl)) * 397 + 185 + tt * 5 + o] = red + b2_s[3 + o];
            }
        }
        __syncthreads();   // protect P_s / tproj_s before next iteration's writes
    }
}

// ------------------------------ K3: BN + mish + gfc2, 8-row batched ------------------------------
__global__ __launch_bounds__(128) void k3(const float* __restrict__ gfc2_w,
                                          const float* __restrict__ gfc2_b,
                                          float* __restrict__ out, int B) {
    __shared__ __align__(16) float m8[80 * 8];
    __shared__ __align__(16) float Wg[80 * 122];
    __shared__ float bs[122];
    __shared__ float sc[80], sh[80];
    int tid = threadIdx.x;
    for (int i = tid; i < 80 * 122; i += 128) {
        int k = i / 122, t = i % 122;
        int r = (t < 5) ? t : (275 + t);
        Wg[i] = gfc2_w[r * 80 + k];
    }
    if (tid < 122) { int r = (tid < 5) ? tid : (275 + tid); bs[tid] = gfc2_b[r]; }
    if (tid < 80) { sc[tid] = d_bnscale[tid]; sh[tid] = d_bnshift[tid]; }
    __syncthreads();
    int nq = (B + 7) >> 3;
    for (int qb = blockIdx.x; qb < nq; qb += gridDim.x) {
        if (tid < 80) {
            #pragma unroll
            for (int rb = 0; rb < 8; rb++) {
                int b = qb * 8 + rb;
                float v = (b < B) ? d_h[(size_t)b * 80 + tid] : 0.f;
                m8[tid * 8 + rb] = mishf(v * sc[tid] + sh[tid]);
            }
        }
        __syncthreads();
        if (tid < 122) {
            float a[8];
            #pragma unroll
            for (int rb = 0; rb < 8; rb++) a[rb] = bs[tid];
            for (int k = 0; k < 80; k++) {
                float4 mA = *(const float4*)(m8 + k * 8);
                float4 mB = *(const float4*)(m8 + k * 8 + 4);
                float w = Wg[k * 122 + tid];
                a[0] += mA.x * w; a[1] += mA.y * w; a[2] += mA.z * w; a[3] += mA.w * w;
                a[4] += mB.x * w; a[5] += mB.y * w; a[6] += mB.z * w; a[7] += mB.w * w;
            }
            int col = (tid < 5) ? tid : (275 + tid);
            #pragma unroll
            for (int rb = 0; rb < 8; rb++) {
                int b = qb * 8 + rb;
                if (b < B) out[(size_t)b * 397 + col] = a[rb];
            }
        }
        __syncthreads();
    }
}

// ------------------------------ launch ------------------------------
extern "C" void kernel_launch(void* const* d_in, const int* in_sizes, int n_in,
                              void* d_out, int out_size) {
    const float* trunk      = (const float*)d_in[0];
    const float* node_emb   = (const float*)d_in[1];
    const int*   road_pairs = (const int*)d_in[2];
    const int*   tile_nodes = (const int*)d_in[3];
    const float* ln_t_w = (const float*)d_in[4];
    const float* ln_t_b = (const float*)d_in[5];
    const float* ln_n_w = (const float*)d_in[6];
    const float* ln_n_b = (const float*)d_in[7];
    const float* gfc1_w = (const float*)d_in[8];
    const float* gfc1_b = (const float*)d_in[9];
    const float* bn_w   = (const float*)d_in[10];
    const float* bn_b   = (const float*)d_in[11];
    const float* gfc2_w = (const float*)d_in[12];
    const float* gfc2_b = (const float*)d_in[13];
    const float* sett1_w = (const float*)d_in[14];
    const float* sett1_b = (const float*)d_in[15];
    const float* sett2_w = (const float*)d_in[16];
    const float* sett2_b = (const float*)d_in[17];
    const float* city1_w = (const float*)d_in[18];
    const float* city1_b = (const float*)d_in[19];
    const float* city2_w = (const float*)d_in[20];
    const float* city2_b = (const float*)d_in[21];
    const float* road1_w = (const float*)d_in[22];
    const float* road1_b = (const float*)d_in[23];
    const float* road2_w = (const float*)d_in[24];
    const float* road2_b = (const float*)d_in[25];
    const float* rob1_w = (const float*)d_in[26];
    const float* rob1_b = (const float*)d_in[27];
    const float* rob2_w = (const float*)d_in[28];
    const float* rob2_b = (const float*)d_in[29];

    int B = in_sizes[0] / 80;
    if (B > BMAX) B = BMAX;
    float* out = (float*)d_out;
    int nblk1 = (B + 127) / 128;

    cudaFuncSetAttribute(k1, cudaFuncAttributeMaxDynamicSharedMemorySize, K1_SMEM);
    cudaFuncSetAttribute(k2, cudaFuncAttributeMaxDynamicSharedMemorySize, SM_TOTAL);

    k_prep<<<(208 * 80 + 255) / 256, 256>>>(sett1_w, city1_w, road1_w, rob1_w, gfc1_w,
                                            sett1_b, city1_b, road1_b, rob1_b, gfc1_b);
    k1<<<nblk1, 512, K1_SMEM>>>(trunk, ln_t_w, ln_t_b, B);
    k_bn<<<1, 80>>>(bn_w, bn_b, B, nblk1);
    k2<<<K2_GRID, 256, SM_TOTAL>>>(node_emb, ln_n_w, ln_n_b, road_pairs, tile_nodes,
                                   sett2_w, sett2_b, city2_w, city2_b,
                                   road2_w, road2_b, rob2_w, rob2_b, out, B);
    k3<<<K3_GRID, 128>>>(gfc2_w, gfc2_b, out, B);
}